// round 1
// baseline (speedup 1.0000x reference)
#include <cuda_runtime.h>

#define BATCH  8
#define HEADS  16
#define SEQ    1024
#define DMODEL 1024
#define DEPTH  64

// Scratch for projected Q/K/V, layout [BATCH, HEADS, SEQ, DEPTH]
__device__ float g_q[BATCH*HEADS*SEQ*DEPTH];
__device__ float g_k[BATCH*HEADS*SEQ*DEPTH];
__device__ float g_v[BATCH*HEADS*SEQ*DEPTH];

// ---------------------------------------------------------------------------
// Projection GEMM: out[b,h,l,e] = sum_d A[b,l,d] * W[h,e,d]
// A: [BATCH*SEQ, DMODEL] row-major. W: [HEADS*DEPTH, DMODEL] row-major.
// Tile 128x128xK(8). 256 threads, 8x8 per thread.
// ---------------------------------------------------------------------------
__global__ __launch_bounds__(256, 2)
void proj_kernel(const float* __restrict__ A, const float* __restrict__ W,
                 float* __restrict__ out)
{
    __shared__ float As[8][128];
    __shared__ float Ws[8][128];

    const int tid = threadIdx.x;
    const int tx  = tid & 15;        // 16 col groups
    const int ty  = tid >> 4;        // 16 row groups
    const int m0  = blockIdx.y * 128;
    const int n0  = blockIdx.x * 128;

    // global loader: each thread one float4 per tile of A and W
    const int lr = tid >> 1;         // 0..127
    const int lk = (tid & 1) * 4;    // 0 or 4

    const float* Ap = A + (size_t)(m0 + lr) * DMODEL + lk;
    const float* Wp = W + (size_t)(n0 + lr) * DMODEL + lk;

    float acc[8][8];
    #pragma unroll
    for (int i = 0; i < 8; i++)
        #pragma unroll
        for (int j = 0; j < 8; j++) acc[i][j] = 0.f;

    for (int k0 = 0; k0 < DMODEL; k0 += 8) {
        float4 av = *(const float4*)(Ap + k0);
        float4 wv = *(const float4*)(Wp + k0);
        __syncthreads();
        As[lk+0][lr] = av.x; As[lk+1][lr] = av.y;
        As[lk+2][lr] = av.z; As[lk+3][lr] = av.w;
        Ws[lk+0][lr] = wv.x; Ws[lk+1][lr] = wv.y;
        Ws[lk+2][lr] = wv.z; Ws[lk+3][lr] = wv.w;
        __syncthreads();
        #pragma unroll
        for (int kk = 0; kk < 8; kk++) {
            float a[8], b[8];
            *(float4*)(a)     = *(const float4*)&As[kk][ty*8];
            *(float4*)(a + 4) = *(const float4*)&As[kk][ty*8 + 4];
            *(float4*)(b)     = *(const float4*)&Ws[kk][tx*8];
            *(float4*)(b + 4) = *(const float4*)&Ws[kk][tx*8 + 4];
            #pragma unroll
            for (int i = 0; i < 8; i++)
                #pragma unroll
                for (int j = 0; j < 8; j++)
                    acc[i][j] = fmaf(a[i], b[j], acc[i][j]);
        }
    }

    // write to [b, h, l, e]; cols n0+tx*8..+8 never cross a head boundary
    const int n = n0 + tx * 8;
    const int h = n >> 6;
    const int e = n & 63;
    #pragma unroll
    for (int i = 0; i < 8; i++) {
        int m  = m0 + ty * 8 + i;
        int bb = m >> 10;
        int l  = m & 1023;
        float* op = out + (((size_t)(bb * HEADS + h) * SEQ + l) * DEPTH + e);
        *(float4*)(op)     = *(float4*)&acc[i][0];
        *(float4*)(op + 4) = *(float4*)&acc[i][4];
    }
}

// ---------------------------------------------------------------------------
// Flash attention per (b,h): Q[1024,64], K[1024,64], V[1024,64]
// Block: 64 q rows, loops over KV in tiles of 64. 128 threads.
// Thread (tx 0..7, ty 0..15): rows ty*4+i (i<4), cols/dims tx*8+j (j<8).
// Row reductions via shfl over the 8 tx lanes.
// Output layout: [B, L, H*DEPTH]  (transpose(1,2).reshape fused into the store)
// ---------------------------------------------------------------------------
__global__ __launch_bounds__(128)
void attn_kernel(float* __restrict__ out)
{
    extern __shared__ float sm[];
    float (*Qs)[68] = (float(*)[68])(sm);             // [d][r], pre-scaled
    float (*Ks)[68] = (float(*)[68])(sm + 1*64*68);   // [d][c]
    float (*Vs)[68] = (float(*)[68])(sm + 2*64*68);   // [c][e]
    float (*Ps)[68] = (float(*)[68])(sm + 3*64*68);   // [c][r] (transposed P)

    const int tid = threadIdx.x;
    const int tx  = tid & 7;
    const int ty  = tid >> 3;
    const int qt  = blockIdx.x;
    const int h   = blockIdx.y;
    const int b   = blockIdx.z;

    const size_t base = (size_t)(b * HEADS + h) * SEQ * DEPTH;
    const float* Qg = g_q + base;
    const float* Kg = g_k + base;
    const float* Vg = g_v + base;

    const int lr = tid >> 1;          // 0..63 (row of 64-row tile)
    const int lc = (tid & 1) * 32;    // half of the 64-wide depth

    // Load Q tile once, transposed + pre-scaled by 1/sqrt(64)
    {
        const float* qp = Qg + (size_t)(qt * 64 + lr) * DEPTH + lc;
        #pragma unroll
        for (int q = 0; q < 8; q++) {
            float4 v = *(const float4*)(qp + q * 4);
            Qs[lc + q*4 + 0][lr] = v.x * 0.125f;
            Qs[lc + q*4 + 1][lr] = v.y * 0.125f;
            Qs[lc + q*4 + 2][lr] = v.z * 0.125f;
            Qs[lc + q*4 + 3][lr] = v.w * 0.125f;
        }
    }

    float m_i[4], l_i[4], o[4][8];
    #pragma unroll
    for (int i = 0; i < 4; i++) {
        m_i[i] = -1e30f; l_i[i] = 0.f;
        #pragma unroll
        for (int j = 0; j < 8; j++) o[i][j] = 0.f;
    }

    for (int kv0 = 0; kv0 < SEQ; kv0 += 64) {
        __syncthreads();   // previous PV finished with Vs/Ps
        // Load K (transposed) and V tiles
        {
            const float* kp = Kg + (size_t)(kv0 + lr) * DEPTH + lc;
            const float* vp = Vg + (size_t)(kv0 + lr) * DEPTH + lc;
            #pragma unroll
            for (int q = 0; q < 8; q++) {
                float4 kvv = *(const float4*)(kp + q * 4);
                Ks[lc + q*4 + 0][lr] = kvv.x;
                Ks[lc + q*4 + 1][lr] = kvv.y;
                Ks[lc + q*4 + 2][lr] = kvv.z;
                Ks[lc + q*4 + 3][lr] = kvv.w;
                float4 vv = *(const float4*)(vp + q * 4);
                *(float4*)&Vs[lr][lc + q*4] = vv;
            }
        }
        __syncthreads();

        // S = (Q*scale) K^T   (4 rows x 8 cols per thread)
        float s[4][8];
        #pragma unroll
        for (int i = 0; i < 4; i++)
            #pragma unroll
            for (int j = 0; j < 8; j++) s[i][j] = 0.f;

        #pragma unroll 8
        for (int d = 0; d < 64; d++) {
            float4 qv = *(const float4*)&Qs[d][ty*4];
            float kv[8];
            *(float4*)(kv)     = *(const float4*)&Ks[d][tx*8];
            *(float4*)(kv + 4) = *(const float4*)&Ks[d][tx*8 + 4];
            float qa[4] = {qv.x, qv.y, qv.z, qv.w};
            #pragma unroll
            for (int i = 0; i < 4; i++)
                #pragma unroll
                for (int j = 0; j < 8; j++)
                    s[i][j] = fmaf(qa[i], kv[j], s[i][j]);
        }

        // Online softmax update
        #pragma unroll
        for (int i = 0; i < 4; i++) {
            float mx = s[i][0];
            #pragma unroll
            for (int j = 1; j < 8; j++) mx = fmaxf(mx, s[i][j]);
            mx = fmaxf(mx, __shfl_xor_sync(0xffffffffu, mx, 1));
            mx = fmaxf(mx, __shfl_xor_sync(0xffffffffu, mx, 2));
            mx = fmaxf(mx, __shfl_xor_sync(0xffffffffu, mx, 4));
            float mnew = fmaxf(m_i[i], mx);
            float corr = __expf(m_i[i] - mnew);
            m_i[i] = mnew;
            float rs = 0.f;
            #pragma unroll
            for (int j = 0; j < 8; j++) {
                float p = __expf(s[i][j] - mnew);
                s[i][j] = p;
                rs += p;
            }
            rs += __shfl_xor_sync(0xffffffffu, rs, 1);
            rs += __shfl_xor_sync(0xffffffffu, rs, 2);
            rs += __shfl_xor_sync(0xffffffffu, rs, 4);
            l_i[i] = l_i[i] * corr + rs;
            #pragma unroll
            for (int j = 0; j < 8; j++) o[i][j] *= corr;
        }

        // Stage P transposed: Ps[c][r]
        #pragma unroll
        for (int j = 0; j < 8; j++) {
            float4 pv = make_float4(s[0][j], s[1][j], s[2][j], s[3][j]);
            *(float4*)&Ps[tx*8 + j][ty*4] = pv;
        }
        __syncthreads();

        // O += P V   (4 rows x 8 dims per thread)
        #pragma unroll 8
        for (int c = 0; c < 64; c++) {
            float4 pv = *(const float4*)&Ps[c][ty*4];
            float vv[8];
            *(float4*)(vv)     = *(const float4*)&Vs[c][tx*8];
            *(float4*)(vv + 4) = *(const float4*)&Vs[c][tx*8 + 4];
            float pa[4] = {pv.x, pv.y, pv.z, pv.w};
            #pragma unroll
            for (int i = 0; i < 4; i++)
                #pragma unroll
                for (int j = 0; j < 8; j++)
                    o[i][j] = fmaf(pa[i], vv[j], o[i][j]);
        }
    }

    // Epilogue: normalize and store to [B, L, H*DEPTH]
    #pragma unroll
    for (int i = 0; i < 4; i++) {
        float inv = 1.f / l_i[i];
        int r = qt * 64 + ty*4 + i;
        float* op = out + ((size_t)b * SEQ + r) * (HEADS*DEPTH) + h * DEPTH + tx * 8;
        float4 v0 = make_float4(o[i][0]*inv, o[i][1]*inv, o[i][2]*inv, o[i][3]*inv);
        float4 v1 = make_float4(o[i][4]*inv, o[i][5]*inv, o[i][6]*inv, o[i][7]*inv);
        *(float4*)(op)     = v0;
        *(float4*)(op + 4) = v1;
    }
}

// ---------------------------------------------------------------------------
extern "C" void kernel_launch(void* const* d_in, const int* in_sizes, int n_in,
                              void* d_out, int out_size)
{
    const float* query  = (const float*)d_in[0];
    const float* keys   = (const float*)d_in[1];
    const float* values = (const float*)d_in[2];
    const float* Wq     = (const float*)d_in[3];
    const float* Wk     = (const float*)d_in[4];
    const float* Wv     = (const float*)d_in[5];
    float* out = (float*)d_out;

    float *qb, *kb, *vb;
    cudaGetSymbolAddress((void**)&qb, g_q);
    cudaGetSymbolAddress((void**)&kb, g_k);
    cudaGetSymbolAddress((void**)&vb, g_v);

    static int attr_done = 0;
    (void)attr_done;
    cudaFuncSetAttribute(attn_kernel,
                         cudaFuncAttributeMaxDynamicSharedMemorySize,
                         4 * 64 * 68 * sizeof(float));

    dim3 pgrid(DMODEL / 128, (BATCH * SEQ) / 128);   // (8, 64)
    proj_kernel<<<pgrid, 256>>>(query,  Wq, qb);
    proj_kernel<<<pgrid, 256>>>(keys,   Wk, kb);
    proj_kernel<<<pgrid, 256>>>(values, Wv, vb);

    dim3 agrid(SEQ / 64, HEADS, BATCH);               // (16, 16, 8)
    attn_kernel<<<agrid, 128, 4 * 64 * 68 * sizeof(float)>>>(out);
}

// round 3
// speedup vs baseline: 1.4066x; 1.4066x over previous
#include <cuda_runtime.h>
#include <cuda_bf16.h>
#include <cstdint>

#define BATCH  8
#define HEADS  16
#define SEQ    1024
#define DMODEL 1024
#define DEPTH  64

// Scratch for projected Q/K/V, layout [BATCH, HEADS, SEQ, DEPTH], fp32
__device__ float g_q[BATCH*HEADS*SEQ*DEPTH];
__device__ float g_k[BATCH*HEADS*SEQ*DEPTH];
__device__ float g_v[BATCH*HEADS*SEQ*DEPTH];

// ===========================================================================
// Warp-MMA helpers (base PTX, valid at compute_103: no 'a'-only features)
// ===========================================================================
__device__ __forceinline__ uint32_t smem_u32(const void* p) {
    uint32_t a;
    asm("{ .reg .u64 t; cvta.to.shared.u64 t, %1; cvt.u32.u64 %0, t; }"
        : "=r"(a) : "l"(p));
    return a;
}

__device__ __forceinline__ void ldsm4(uint32_t* r, uint32_t addr) {
    asm volatile("ldmatrix.sync.aligned.m8n8.x4.shared.b16 {%0,%1,%2,%3}, [%4];"
                 : "=r"(r[0]), "=r"(r[1]), "=r"(r[2]), "=r"(r[3]) : "r"(addr));
}

__device__ __forceinline__ void mma16816(float* d, const uint32_t* a, const uint32_t* b) {
    asm volatile("mma.sync.aligned.m16n8k16.row.col.f32.bf16.bf16.f32 "
                 "{%0,%1,%2,%3}, {%4,%5,%6,%7}, {%8,%9}, {%0,%1,%2,%3};"
                 : "+f"(d[0]), "+f"(d[1]), "+f"(d[2]), "+f"(d[3])
                 : "r"(a[0]), "r"(a[1]), "r"(a[2]), "r"(a[3]),
                   "r"(b[0]), "r"(b[1]));
}

__device__ __forceinline__ uint32_t swz(uint32_t bo) {
    return bo ^ ((bo >> 3) & 0x70);
}

// fp32 -> (hi bf16, lo bf16) for two values, packed (x0 in low 16 bits)
__device__ __forceinline__ void split2(float x0, float x1, uint32_t& hi, uint32_t& lo) {
    __nv_bfloat162 h = __floats2bfloat162_rn(x0, x1);
    hi = *reinterpret_cast<uint32_t*>(&h);
    float r0 = x0 - __bfloat162float(h.x);
    float r1 = x1 - __bfloat162float(h.y);
    __nv_bfloat162 l = __floats2bfloat162_rn(r0, r1);
    lo = *reinterpret_cast<uint32_t*>(&l);
}

// ===========================================================================
// mma.sync projection GEMM: out[(b,h),l,e] = sum_d A[(b,l),d] * W[(h,e),d]
// A: [8192,1024] fp32, W: [1024,1024] fp32.  CTA tile 128x128, K-chunk 64.
// bf16 hi/lo split, 3 mma passes (hh + lh + hl), fp32 register accumulators.
// 8 warps: warp grid 4(M) x 2(N), warp tile 32x64.
// ===========================================================================
#define OFF_AH 0
#define OFF_AL 16384
#define OFF_BH 32768
#define OFF_BL 49152
#define PROJ_SMEM 65536

__global__ __launch_bounds__(256, 1)
void mma_proj_kernel(const float* __restrict__ A, const float* __restrict__ W,
                     float* __restrict__ out)
{
    extern __shared__ char smc[];
    const uint32_t sbase = smem_u32(smc);
    const int tid  = threadIdx.x;
    const int lane = tid & 31;
    const int wid  = tid >> 5;
    const int n0   = blockIdx.x * 128;
    const int m0   = blockIdx.y * 128;

    const int wm = (wid & 3) * 32;    // warp M offset in CTA tile
    const int wn = (wid >> 2) * 64;   // warp N offset in CTA tile

    const float* Ab = A + (size_t)m0 * DMODEL;
    const float* Wb = W + (size_t)n0 * DMODEL;

    float acc[2][8][4];
    #pragma unroll
    for (int mt = 0; mt < 2; mt++)
        #pragma unroll
        for (int nt = 0; nt < 8; nt++)
            #pragma unroll
            for (int r = 0; r < 4; r++) acc[mt][nt][r] = 0.f;

    // Per-lane invariant parts of ldmatrix addresses (byte offsets in tile)
    // A (x4 over 16x16): rows lane&15, col half lane>>4
    const uint32_t a_row = wm + (lane & 15);
    const uint32_t a_kb0 = (lane >> 4) << 4;            // 0 or 16 bytes
    // B (x4 over two n8 x k16): j = lane>>3, r = lane&7
    const uint32_t b_j   = lane >> 3;
    const uint32_t b_row = wn + (lane & 7) + ((b_j >> 1) << 3);  // + second n8 via mt loop offset
    const uint32_t b_kb0 = (b_j & 1) << 4;              // 0 or 16 bytes

    // Loader indices (each thread: one A float4 + one W float4 per iter)
    const int lr_base = tid >> 4;        // advances by 16 per iter
    const int lf4     = tid & 15;        // float4 index within 64-col row

    for (int c = 0; c < 16; ++c) {
        const int k0 = c * 64;

        __syncthreads();   // previous chunk's mma done with smem
        // ---- load + split + swizzled store: A[128x64], W[128x64] ----
        #pragma unroll
        for (int it = 0; it < 8; ++it) {
            int r = lr_base + it * 16;
            uint32_t bo = r * 128 + lf4 * 8;
            uint32_t sw = swz(bo);

            float4 va = *(const float4*)(Ab + (size_t)r * DMODEL + k0 + lf4 * 4);
            uint32_t h01, l01, h23, l23;
            split2(va.x, va.y, h01, l01);
            split2(va.z, va.w, h23, l23);
            *(uint2*)(smc + OFF_AH + sw) = make_uint2(h01, h23);
            *(uint2*)(smc + OFF_AL + sw) = make_uint2(l01, l23);

            float4 vb = *(const float4*)(Wb + (size_t)r * DMODEL + k0 + lf4 * 4);
            split2(vb.x, vb.y, h01, l01);
            split2(vb.z, vb.w, h23, l23);
            *(uint2*)(smc + OFF_BH + sw) = make_uint2(h01, h23);
            *(uint2*)(smc + OFF_BL + sw) = make_uint2(l01, l23);
        }
        __syncthreads();

        // ---- 4 k16 steps over the 64-wide chunk ----
        #pragma unroll
        for (int kk = 0; kk < 4; ++kk) {
            const uint32_t kb = kk * 32;   // bytes: 16 bf16 per k16

            uint32_t ah[2][4], al[2][4];
            #pragma unroll
            for (int mt = 0; mt < 2; mt++) {
                uint32_t bo = (a_row + mt * 16) * 128 + kb + a_kb0;
                ldsm4(ah[mt], sbase + OFF_AH + swz(bo));
                ldsm4(al[mt], sbase + OFF_AL + swz(bo));
            }

            uint32_t bh[8][2], bl[8][2];
            #pragma unroll
            for (int np = 0; np < 4; np++) {  // each x4 covers two n8 tiles
                uint32_t bo = (b_row + np * 16) * 128 + kb + b_kb0;
                uint32_t t[4];
                ldsm4(t, sbase + OFF_BH + swz(bo));
                bh[np*2+0][0] = t[0]; bh[np*2+0][1] = t[1];
                bh[np*2+1][0] = t[2]; bh[np*2+1][1] = t[3];
                ldsm4(t, sbase + OFF_BL + swz(bo));
                bl[np*2+0][0] = t[0]; bl[np*2+0][1] = t[1];
                bl[np*2+1][0] = t[2]; bl[np*2+1][1] = t[3];
            }

            #pragma unroll
            for (int mt = 0; mt < 2; mt++)
                #pragma unroll
                for (int nt = 0; nt < 8; nt++) {
                    mma16816(acc[mt][nt], ah[mt], bh[nt]);
                    mma16816(acc[mt][nt], al[mt], bh[nt]);
                    mma16816(acc[mt][nt], ah[mt], bl[nt]);
                }
        }
    }

    // ---- epilogue: write fp32 directly to [b,h,l,e] ----
    const int gid = lane >> 2;
    const int qid = lane & 3;
    #pragma unroll
    for (int mt = 0; mt < 2; mt++) {
        int m  = m0 + wm + mt * 16 + gid;
        int bb = m >> 10;
        int l  = m & 1023;
        #pragma unroll
        for (int nt = 0; nt < 8; nt++) {
            int n = n0 + wn + nt * 8 + qid * 2;
            int h = n >> 6;
            int e = n & 63;
            float* p = out + (((size_t)(bb * HEADS + h) * SEQ + l) * DEPTH + e);
            *(float2*)p = make_float2(acc[mt][nt][0], acc[mt][nt][1]);
            *(float2*)(p + 8 * DEPTH) = make_float2(acc[mt][nt][2], acc[mt][nt][3]);
        }
    }
}

// ===========================================================================
// Flash attention per (b,h) — unchanged fp32 SIMT version (known correct)
// ===========================================================================
__global__ __launch_bounds__(128)
void attn_kernel(float* __restrict__ out)
{
    extern __shared__ float sm[];
    float (*Qs)[68] = (float(*)[68])(sm);
    float (*Ks)[68] = (float(*)[68])(sm + 1*64*68);
    float (*Vs)[68] = (float(*)[68])(sm + 2*64*68);
    float (*Ps)[68] = (float(*)[68])(sm + 3*64*68);

    const int tid = threadIdx.x;
    const int tx  = tid & 7;
    const int ty  = tid >> 3;
    const int qt  = blockIdx.x;
    const int h   = blockIdx.y;
    const int b   = blockIdx.z;

    const size_t base = (size_t)(b * HEADS + h) * SEQ * DEPTH;
    const float* Qg = g_q + base;
    const float* Kg = g_k + base;
    const float* Vg = g_v + base;

    const int lr = tid >> 1;
    const int lc = (tid & 1) * 32;

    {
        const float* qp = Qg + (size_t)(qt * 64 + lr) * DEPTH + lc;
        #pragma unroll
        for (int q = 0; q < 8; q++) {
            float4 v = *(const float4*)(qp + q * 4);
            Qs[lc + q*4 + 0][lr] = v.x * 0.125f;
            Qs[lc + q*4 + 1][lr] = v.y * 0.125f;
            Qs[lc + q*4 + 2][lr] = v.z * 0.125f;
            Qs[lc + q*4 + 3][lr] = v.w * 0.125f;
        }
    }

    float m_i[4], l_i[4], o[4][8];
    #pragma unroll
    for (int i = 0; i < 4; i++) {
        m_i[i] = -1e30f; l_i[i] = 0.f;
        #pragma unroll
        for (int j = 0; j < 8; j++) o[i][j] = 0.f;
    }

    for (int kv0 = 0; kv0 < SEQ; kv0 += 64) {
        __syncthreads();
        {
            const float* kp = Kg + (size_t)(kv0 + lr) * DEPTH + lc;
            const float* vp = Vg + (size_t)(kv0 + lr) * DEPTH + lc;
            #pragma unroll
            for (int q = 0; q < 8; q++) {
                float4 kvv = *(const float4*)(kp + q * 4);
                Ks[lc + q*4 + 0][lr] = kvv.x;
                Ks[lc + q*4 + 1][lr] = kvv.y;
                Ks[lc + q*4 + 2][lr] = kvv.z;
                Ks[lc + q*4 + 3][lr] = kvv.w;
                float4 vv = *(const float4*)(vp + q * 4);
                *(float4*)&Vs[lr][lc + q*4] = vv;
            }
        }
        __syncthreads();

        float s[4][8];
        #pragma unroll
        for (int i = 0; i < 4; i++)
            #pragma unroll
            for (int j = 0; j < 8; j++) s[i][j] = 0.f;

        #pragma unroll 8
        for (int d = 0; d < 64; d++) {
            float4 qv = *(const float4*)&Qs[d][ty*4];
            float kv[8];
            *(float4*)(kv)     = *(const float4*)&Ks[d][tx*8];
            *(float4*)(kv + 4) = *(const float4*)&Ks[d][tx*8 + 4];
            float qa[4] = {qv.x, qv.y, qv.z, qv.w};
            #pragma unroll
            for (int i = 0; i < 4; i++)
                #pragma unroll
                for (int j = 0; j < 8; j++)
                    s[i][j] = fmaf(qa[i], kv[j], s[i][j]);
        }

        #pragma unroll
        for (int i = 0; i < 4; i++) {
            float mx = s[i][0];
            #pragma unroll
            for (int j = 1; j < 8; j++) mx = fmaxf(mx, s[i][j]);
            mx = fmaxf(mx, __shfl_xor_sync(0xffffffffu, mx, 1));
            mx = fmaxf(mx, __shfl_xor_sync(0xffffffffu, mx, 2));
            mx = fmaxf(mx, __shfl_xor_sync(0xffffffffu, mx, 4));
            float mnew = fmaxf(m_i[i], mx);
            float corr = __expf(m_i[i] - mnew);
            m_i[i] = mnew;
            float rs = 0.f;
            #pragma unroll
            for (int j = 0; j < 8; j++) {
                float p = __expf(s[i][j] - mnew);
                s[i][j] = p;
                rs += p;
            }
            rs += __shfl_xor_sync(0xffffffffu, rs, 1);
            rs += __shfl_xor_sync(0xffffffffu, rs, 2);
            rs += __shfl_xor_sync(0xffffffffu, rs, 4);
            l_i[i] = l_i[i] * corr + rs;
            #pragma unroll
            for (int j = 0; j < 8; j++) o[i][j] *= corr;
        }

        #pragma unroll
        for (int j = 0; j < 8; j++) {
            float4 pv = make_float4(s[0][j], s[1][j], s[2][j], s[3][j]);
            *(float4*)&Ps[tx*8 + j][ty*4] = pv;
        }
        __syncthreads();

        #pragma unroll 8
        for (int c = 0; c < 64; c++) {
            float4 pv = *(const float4*)&Ps[c][ty*4];
            float vv[8];
            *(float4*)(vv)     = *(const float4*)&Vs[c][tx*8];
            *(float4*)(vv + 4) = *(const float4*)&Vs[c][tx*8 + 4];
            float pa[4] = {pv.x, pv.y, pv.z, pv.w};
            #pragma unroll
            for (int i = 0; i < 4; i++)
                #pragma unroll
                for (int j = 0; j < 8; j++)
                    o[i][j] = fmaf(pa[i], vv[j], o[i][j]);
        }
    }

    #pragma unroll
    for (int i = 0; i < 4; i++) {
        float inv = 1.f / l_i[i];
        int r = qt * 64 + ty*4 + i;
        float* op = out + ((size_t)b * SEQ + r) * (HEADS*DEPTH) + h * DEPTH + tx * 8;
        float4 v0 = make_float4(o[i][0]*inv, o[i][1]*inv, o[i][2]*inv, o[i][3]*inv);
        float4 v1 = make_float4(o[i][4]*inv, o[i][5]*inv, o[i][6]*inv, o[i][7]*inv);
        *(float4*)(op)     = v0;
        *(float4*)(op + 4) = v1;
    }
}

// ===========================================================================
extern "C" void kernel_launch(void* const* d_in, const int* in_sizes, int n_in,
                              void* d_out, int out_size)
{
    const float* query  = (const float*)d_in[0];
    const float* keys   = (const float*)d_in[1];
    const float* values = (const float*)d_in[2];
    const float* Wq     = (const float*)d_in[3];
    const float* Wk     = (const float*)d_in[4];
    const float* Wv     = (const float*)d_in[5];
    float* out = (float*)d_out;

    float *qb, *kb, *vb;
    cudaGetSymbolAddress((void**)&qb, g_q);
    cudaGetSymbolAddress((void**)&kb, g_k);
    cudaGetSymbolAddress((void**)&vb, g_v);

    cudaFuncSetAttribute(mma_proj_kernel,
                         cudaFuncAttributeMaxDynamicSharedMemorySize, PROJ_SMEM);
    cudaFuncSetAttribute(attn_kernel,
                         cudaFuncAttributeMaxDynamicSharedMemorySize,
                         4 * 64 * 68 * sizeof(float));

    dim3 pgrid(DMODEL / 128, (BATCH * SEQ) / 128);   // (8, 64)
    mma_proj_kernel<<<pgrid, 256, PROJ_SMEM>>>(query,  Wq, qb);
    mma_proj_kernel<<<pgrid, 256, PROJ_SMEM>>>(keys,   Wk, kb);
    mma_proj_kernel<<<pgrid, 256, PROJ_SMEM>>>(values, Wv, vb);

    dim3 agrid(SEQ / 64, HEADS, BATCH);              // (16, 16, 8)
    attn_kernel<<<agrid, 128, 4 * 64 * 68 * sizeof(float)>>>(out);
}

// round 4
// speedup vs baseline: 3.2536x; 2.3132x over previous
#include <cuda_runtime.h>
#include <cuda_bf16.h>
#include <cstdint>

#define BATCH  8
#define HEADS  16
#define SEQ    1024
#define DMODEL 1024
#define DEPTH  64

// Scratch for projected Q/K/V, layout [BATCH, HEADS, SEQ, DEPTH], fp32
__device__ float g_q[BATCH*HEADS*SEQ*DEPTH];
__device__ float g_k[BATCH*HEADS*SEQ*DEPTH];
__device__ float g_v[BATCH*HEADS*SEQ*DEPTH];

// ===========================================================================
// Warp-MMA helpers (base PTX, valid at compute_103)
// ===========================================================================
__device__ __forceinline__ uint32_t smem_u32(const void* p) {
    uint32_t a;
    asm("{ .reg .u64 t; cvta.to.shared.u64 t, %1; cvt.u32.u64 %0, t; }"
        : "=r"(a) : "l"(p));
    return a;
}

__device__ __forceinline__ void ldsm4(uint32_t* r, uint32_t addr) {
    asm volatile("ldmatrix.sync.aligned.m8n8.x4.shared.b16 {%0,%1,%2,%3}, [%4];"
                 : "=r"(r[0]), "=r"(r[1]), "=r"(r[2]), "=r"(r[3]) : "r"(addr));
}

__device__ __forceinline__ void ldsm4t(uint32_t* r, uint32_t addr) {
    asm volatile("ldmatrix.sync.aligned.m8n8.x4.trans.shared.b16 {%0,%1,%2,%3}, [%4];"
                 : "=r"(r[0]), "=r"(r[1]), "=r"(r[2]), "=r"(r[3]) : "r"(addr));
}

__device__ __forceinline__ void mma16816(float* d, const uint32_t* a, const uint32_t* b) {
    asm volatile("mma.sync.aligned.m16n8k16.row.col.f32.bf16.bf16.f32 "
                 "{%0,%1,%2,%3}, {%4,%5,%6,%7}, {%8,%9}, {%0,%1,%2,%3};"
                 : "+f"(d[0]), "+f"(d[1]), "+f"(d[2]), "+f"(d[3])
                 : "r"(a[0]), "r"(a[1]), "r"(a[2]), "r"(a[3]),
                   "r"(b[0]), "r"(b[1]));
}

__device__ __forceinline__ uint32_t swz(uint32_t bo) {
    return bo ^ ((bo >> 3) & 0x70);
}

__device__ __forceinline__ float ex2(float x) {
    float r;
    asm("ex2.approx.f32 %0, %1;" : "=f"(r) : "f"(x));
    return r;
}

// fp32 -> (hi bf16, lo bf16) for two values, packed (x0 in low 16 bits)
__device__ __forceinline__ void split2(float x0, float x1, uint32_t& hi, uint32_t& lo) {
    __nv_bfloat162 h = __floats2bfloat162_rn(x0, x1);
    hi = *reinterpret_cast<uint32_t*>(&h);
    float r0 = x0 - __bfloat162float(h.x);
    float r1 = x1 - __bfloat162float(h.y);
    __nv_bfloat162 l = __floats2bfloat162_rn(r0, r1);
    lo = *reinterpret_cast<uint32_t*>(&l);
}

__device__ __forceinline__ uint32_t packbf(float lo, float hi) {
    __nv_bfloat162 h = __floats2bfloat162_rn(lo, hi);   // .x = lo -> low 16 bits
    return *reinterpret_cast<uint32_t*>(&h);
}
__device__ __forceinline__ float ubf_lo(uint32_t p) { return __uint_as_float(p << 16); }
__device__ __forceinline__ float ubf_hi(uint32_t p) { return __uint_as_float(p & 0xFFFF0000u); }

// ===========================================================================
// mma.sync projection GEMM (unchanged from R3, known correct)
// ===========================================================================
#define OFF_AH 0
#define OFF_AL 16384
#define OFF_BH 32768
#define OFF_BL 49152
#define PROJ_SMEM 65536

__global__ __launch_bounds__(256, 1)
void mma_proj_kernel(const float* __restrict__ A, const float* __restrict__ W,
                     float* __restrict__ out)
{
    extern __shared__ char smc[];
    const uint32_t sbase = smem_u32(smc);
    const int tid  = threadIdx.x;
    const int lane = tid & 31;
    const int wid  = tid >> 5;
    const int n0   = blockIdx.x * 128;
    const int m0   = blockIdx.y * 128;

    const int wm = (wid & 3) * 32;
    const int wn = (wid >> 2) * 64;

    const float* Ab = A + (size_t)m0 * DMODEL;
    const float* Wb = W + (size_t)n0 * DMODEL;

    float acc[2][8][4];
    #pragma unroll
    for (int mt = 0; mt < 2; mt++)
        #pragma unroll
        for (int nt = 0; nt < 8; nt++)
            #pragma unroll
            for (int r = 0; r < 4; r++) acc[mt][nt][r] = 0.f;

    const uint32_t a_row = wm + (lane & 15);
    const uint32_t a_kb0 = (lane >> 4) << 4;
    const uint32_t b_j   = lane >> 3;
    const uint32_t b_row = wn + (lane & 7) + ((b_j >> 1) << 3);
    const uint32_t b_kb0 = (b_j & 1) << 4;

    const int lr_base = tid >> 4;
    const int lf4     = tid & 15;

    for (int c = 0; c < 16; ++c) {
        const int k0 = c * 64;

        __syncthreads();
        #pragma unroll
        for (int it = 0; it < 8; ++it) {
            int r = lr_base + it * 16;
            uint32_t bo = r * 128 + lf4 * 8;
            uint32_t sw = swz(bo);

            float4 va = *(const float4*)(Ab + (size_t)r * DMODEL + k0 + lf4 * 4);
            uint32_t h01, l01, h23, l23;
            split2(va.x, va.y, h01, l01);
            split2(va.z, va.w, h23, l23);
            *(uint2*)(smc + OFF_AH + sw) = make_uint2(h01, h23);
            *(uint2*)(smc + OFF_AL + sw) = make_uint2(l01, l23);

            float4 vb = *(const float4*)(Wb + (size_t)r * DMODEL + k0 + lf4 * 4);
            split2(vb.x, vb.y, h01, l01);
            split2(vb.z, vb.w, h23, l23);
            *(uint2*)(smc + OFF_BH + sw) = make_uint2(h01, h23);
            *(uint2*)(smc + OFF_BL + sw) = make_uint2(l01, l23);
        }
        __syncthreads();

        #pragma unroll
        for (int kk = 0; kk < 4; ++kk) {
            const uint32_t kb = kk * 32;

            uint32_t ah[2][4], al[2][4];
            #pragma unroll
            for (int mt = 0; mt < 2; mt++) {
                uint32_t bo = (a_row + mt * 16) * 128 + kb + a_kb0;
                ldsm4(ah[mt], sbase + OFF_AH + swz(bo));
                ldsm4(al[mt], sbase + OFF_AL + swz(bo));
            }

            uint32_t bh[8][2], bl[8][2];
            #pragma unroll
            for (int np = 0; np < 4; np++) {
                uint32_t bo = (b_row + np * 16) * 128 + kb + b_kb0;
                uint32_t t[4];
                ldsm4(t, sbase + OFF_BH + swz(bo));
                bh[np*2+0][0] = t[0]; bh[np*2+0][1] = t[1];
                bh[np*2+1][0] = t[2]; bh[np*2+1][1] = t[3];
                ldsm4(t, sbase + OFF_BL + swz(bo));
                bl[np*2+0][0] = t[0]; bl[np*2+0][1] = t[1];
                bl[np*2+1][0] = t[2]; bl[np*2+1][1] = t[3];
            }

            #pragma unroll
            for (int mt = 0; mt < 2; mt++)
                #pragma unroll
                for (int nt = 0; nt < 8; nt++) {
                    mma16816(acc[mt][nt], ah[mt], bh[nt]);
                    mma16816(acc[mt][nt], al[mt], bh[nt]);
                    mma16816(acc[mt][nt], ah[mt], bl[nt]);
                }
        }
    }

    const int gid = lane >> 2;
    const int qid = lane & 3;
    #pragma unroll
    for (int mt = 0; mt < 2; mt++) {
        int m  = m0 + wm + mt * 16 + gid;
        int bb = m >> 10;
        int l  = m & 1023;
        #pragma unroll
        for (int nt = 0; nt < 8; nt++) {
            int n = n0 + wn + nt * 8 + qid * 2;
            int h = n >> 6;
            int e = n & 63;
            float* p = out + (((size_t)(bb * HEADS + h) * SEQ + l) * DEPTH + e);
            *(float2*)p = make_float2(acc[mt][nt][0], acc[mt][nt][1]);
            *(float2*)(p + 8 * DEPTH) = make_float2(acc[mt][nt][2], acc[mt][nt][3]);
        }
    }
}

// ===========================================================================
// mma.sync flash attention per (b,h).
// CTA: 128 q rows, 8 warps (warp = m16). KV tiles of 64.
// Q pre-scaled by 0.125*log2e; softmax in log2 domain via ex2.approx.
// S = QhKh + QlKh + QhKl;  O += PhVh + PlVh + PhVl (P re-split in regs).
// smem: QH 16K | QL 16K | KH 8K | KL 8K | VH 8K | VL 8K = 64 KB
// ===========================================================================
#define AQH 0
#define AQL 16384
#define AKH 32768
#define AKL 40960
#define AVH 49152
#define AVL 57344
#define ATTN_SMEM 65536
#define QSCALE 0.18033688f   /* 0.125 * log2(e) */

__global__ __launch_bounds__(256)
void mma_attn_kernel(float* __restrict__ out)
{
    extern __shared__ char smc[];
    const uint32_t sb = smem_u32(smc);
    const int tid  = threadIdx.x;
    const int lane = tid & 31;
    const int wid  = tid >> 5;
    const int qt   = blockIdx.x;
    const int h    = blockIdx.y;
    const int b    = blockIdx.z;

    const size_t base = (size_t)(b * HEADS + h) * SEQ * DEPTH;
    const float* Qg = g_q + base + (size_t)(qt * 128) * DEPTH;
    const float* Kg = g_k + base;
    const float* Vg = g_v + base;

    const int lr = tid >> 4;      // loader row stride base
    const int lf4 = tid & 15;     // float4 index within 64-wide row

    // ---- load Q tile (128x64), scaled + split, once ----
    #pragma unroll
    for (int it = 0; it < 8; ++it) {
        int r = lr + it * 16;
        float4 v = *(const float4*)(Qg + (size_t)r * DEPTH + lf4 * 4);
        v.x *= QSCALE; v.y *= QSCALE; v.z *= QSCALE; v.w *= QSCALE;
        uint32_t h01, l01, h23, l23;
        split2(v.x, v.y, h01, l01);
        split2(v.z, v.w, h23, l23);
        uint32_t sw = swz(r * 128 + lf4 * 8);
        *(uint2*)(smc + AQH + sw) = make_uint2(h01, h23);
        *(uint2*)(smc + AQL + sw) = make_uint2(l01, l23);
    }

    // per-warp fragment address components
    const int wm = wid * 16;
    const uint32_t qa_row = wm + (lane & 15);
    const uint32_t qa_cb  = (lane >> 4) << 4;
    const uint32_t kb_row = (lane & 7) + (((lane >> 4) & 1) << 3);
    const uint32_t kb_cb  = ((lane >> 3) & 1) << 4;
    const uint32_t va_row = (((lane >> 3) & 1) << 3) + (lane & 7);
    const uint32_t va_cb  = (lane >> 4) << 4;

    float m0 = -1e30f, m1 = -1e30f, l0 = 0.f, l1 = 0.f;
    float o[8][4];
    #pragma unroll
    for (int j = 0; j < 8; j++)
        #pragma unroll
        for (int r = 0; r < 4; r++) o[j][r] = 0.f;

    for (int t = 0; t < 16; ++t) {
        __syncthreads();
        // ---- load K,V tile (64x64 each), split ----
        {
            const float* Kt = Kg + (size_t)(t * 64) * DEPTH;
            const float* Vt = Vg + (size_t)(t * 64) * DEPTH;
            #pragma unroll
            for (int it = 0; it < 4; ++it) {
                int idx = tid + it * 256;
                int r   = idx >> 4;
                int f4  = idx & 15;
                uint32_t sw = swz(r * 128 + f4 * 8);

                float4 kv = *(const float4*)(Kt + (size_t)r * DEPTH + f4 * 4);
                uint32_t h01, l01, h23, l23;
                split2(kv.x, kv.y, h01, l01);
                split2(kv.z, kv.w, h23, l23);
                *(uint2*)(smc + AKH + sw) = make_uint2(h01, h23);
                *(uint2*)(smc + AKL + sw) = make_uint2(l01, l23);

                float4 vv = *(const float4*)(Vt + (size_t)r * DEPTH + f4 * 4);
                split2(vv.x, vv.y, h01, l01);
                split2(vv.z, vv.w, h23, l23);
                *(uint2*)(smc + AVH + sw) = make_uint2(h01, h23);
                *(uint2*)(smc + AVL + sw) = make_uint2(l01, l23);
            }
        }
        __syncthreads();

        // ---- S = Q Kt (3 split passes) ----
        float s[8][4];
        #pragma unroll
        for (int j = 0; j < 8; j++)
            #pragma unroll
            for (int r = 0; r < 4; r++) s[j][r] = 0.f;

        #pragma unroll
        for (int kk = 0; kk < 4; ++kk) {
            uint32_t qh[4], ql[4];
            uint32_t qoff = qa_row * 128 + kk * 32 + qa_cb;
            ldsm4(qh, sb + AQH + swz(qoff));
            ldsm4(ql, sb + AQL + swz(qoff));
            #pragma unroll
            for (int np = 0; np < 4; ++np) {
                uint32_t koff = (np * 16 + kb_row) * 128 + kk * 32 + kb_cb;
                uint32_t th[4], tl[4];
                ldsm4(th, sb + AKH + swz(koff));
                ldsm4(tl, sb + AKL + swz(koff));
                mma16816(s[np*2+0], qh, th + 0);
                mma16816(s[np*2+0], ql, th + 0);
                mma16816(s[np*2+0], qh, tl + 0);
                mma16816(s[np*2+1], qh, th + 2);
                mma16816(s[np*2+1], ql, th + 2);
                mma16816(s[np*2+1], qh, tl + 2);
            }
        }

        // ---- online softmax (log2 domain) ----
        float mx0 = s[0][0], mx1 = s[0][2];
        #pragma unroll
        for (int j = 0; j < 8; j++) {
            mx0 = fmaxf(mx0, fmaxf(s[j][0], s[j][1]));
            mx1 = fmaxf(mx1, fmaxf(s[j][2], s[j][3]));
        }
        mx0 = fmaxf(mx0, __shfl_xor_sync(0xffffffffu, mx0, 1));
        mx0 = fmaxf(mx0, __shfl_xor_sync(0xffffffffu, mx0, 2));
        mx1 = fmaxf(mx1, __shfl_xor_sync(0xffffffffu, mx1, 1));
        mx1 = fmaxf(mx1, __shfl_xor_sync(0xffffffffu, mx1, 2));

        float mn0 = fmaxf(m0, mx0), mn1 = fmaxf(m1, mx1);
        float sc0 = ex2(m0 - mn0),  sc1 = ex2(m1 - mn1);
        m0 = mn0; m1 = mn1;

        float rs0 = 0.f, rs1 = 0.f;
        uint32_t ph[8][2], pl[8][2];
        #pragma unroll
        for (int j = 0; j < 8; j++) {
            float p0 = ex2(s[j][0] - m0);
            float p1 = ex2(s[j][1] - m0);
            float p2 = ex2(s[j][2] - m1);
            float p3 = ex2(s[j][3] - m1);
            rs0 += p0 + p1;
            rs1 += p2 + p3;
            ph[j][0] = packbf(p0, p1);
            ph[j][1] = packbf(p2, p3);
            pl[j][0] = packbf(p0 - ubf_lo(ph[j][0]), p1 - ubf_hi(ph[j][0]));
            pl[j][1] = packbf(p2 - ubf_lo(ph[j][1]), p3 - ubf_hi(ph[j][1]));
        }
        rs0 += __shfl_xor_sync(0xffffffffu, rs0, 1);
        rs0 += __shfl_xor_sync(0xffffffffu, rs0, 2);
        rs1 += __shfl_xor_sync(0xffffffffu, rs1, 1);
        rs1 += __shfl_xor_sync(0xffffffffu, rs1, 2);
        l0 = l0 * sc0 + rs0;
        l1 = l1 * sc1 + rs1;
        #pragma unroll
        for (int j = 0; j < 8; j++) {
            o[j][0] *= sc0; o[j][1] *= sc0;
            o[j][2] *= sc1; o[j][3] *= sc1;
        }

        // ---- O += P V (3 split passes), V via trans ldmatrix ----
        #pragma unroll
        for (int ks = 0; ks < 4; ++ks) {
            uint32_t ah[4] = { ph[ks*2][0], ph[ks*2][1], ph[ks*2+1][0], ph[ks*2+1][1] };
            uint32_t al[4] = { pl[ks*2][0], pl[ks*2][1], pl[ks*2+1][0], pl[ks*2+1][1] };
            #pragma unroll
            for (int dg = 0; dg < 4; ++dg) {
                uint32_t voff = (ks * 16 + va_row) * 128 + dg * 32 + va_cb;
                uint32_t th[4], tl[4];
                ldsm4t(th, sb + AVH + swz(voff));
                ldsm4t(tl, sb + AVL + swz(voff));
                mma16816(o[dg*2+0], ah, th + 0);
                mma16816(o[dg*2+0], al, th + 0);
                mma16816(o[dg*2+0], ah, tl + 0);
                mma16816(o[dg*2+1], ah, th + 2);
                mma16816(o[dg*2+1], al, th + 2);
                mma16816(o[dg*2+1], ah, tl + 2);
            }
        }
    }

    // ---- epilogue: normalize, store to [B, L, H*DEPTH] ----
    float inv0 = 1.f / l0, inv1 = 1.f / l1;
    int r0 = qt * 128 + wm + (lane >> 2);
    float* p0 = out + ((size_t)b * SEQ + r0) * (HEADS * DEPTH) + h * DEPTH + (lane & 3) * 2;
    float* p1 = p0 + 8 * (HEADS * DEPTH);
    #pragma unroll
    for (int j = 0; j < 8; j++) {
        *(float2*)(p0 + j * 8) = make_float2(o[j][0] * inv0, o[j][1] * inv0);
        *(float2*)(p1 + j * 8) = make_float2(o[j][2] * inv1, o[j][3] * inv1);
    }
}

// ===========================================================================
extern "C" void kernel_launch(void* const* d_in, const int* in_sizes, int n_in,
                              void* d_out, int out_size)
{
    const float* query  = (const float*)d_in[0];
    const float* keys   = (const float*)d_in[1];
    const float* values = (const float*)d_in[2];
    const float* Wq     = (const float*)d_in[3];
    const float* Wk     = (const float*)d_in[4];
    const float* Wv     = (const float*)d_in[5];
    float* out = (float*)d_out;

    float *qb, *kb, *vb;
    cudaGetSymbolAddress((void**)&qb, g_q);
    cudaGetSymbolAddress((void**)&kb, g_k);
    cudaGetSymbolAddress((void**)&vb, g_v);

    cudaFuncSetAttribute(mma_proj_kernel,
                         cudaFuncAttributeMaxDynamicSharedMemorySize, PROJ_SMEM);
    cudaFuncSetAttribute(mma_attn_kernel,
                         cudaFuncAttributeMaxDynamicSharedMemorySize, ATTN_SMEM);

    dim3 pgrid(DMODEL / 128, (BATCH * SEQ) / 128);   // (8, 64)
    mma_proj_kernel<<<pgrid, 256, PROJ_SMEM>>>(query,  Wq, qb);
    mma_proj_kernel<<<pgrid, 256, PROJ_SMEM>>>(keys,   Wk, kb);
    mma_proj_kernel<<<pgrid, 256, PROJ_SMEM>>>(values, Wv, vb);

    dim3 agrid(SEQ / 128, HEADS, BATCH);             // (8, 16, 8)
    mma_attn_kernel<<<agrid, 256, ATTN_SMEM>>>(out);
}

// round 5
// speedup vs baseline: 3.9474x; 1.2133x over previous
#include <cuda_runtime.h>
#include <cuda_bf16.h>
#include <cstdint>

#define BATCH  8
#define HEADS  16
#define SEQ    1024
#define DMODEL 1024
#define DEPTH  64

#define IN_N   (BATCH*SEQ*DMODEL)      // 8388608  (== BATCH*HEADS*SEQ*DEPTH)
#define W_N    (DMODEL*DMODEL)         // 1048576
#define QSCALE 0.18033688f             /* 0.125 * log2(e) */

// bf16 hi/lo planes: presplit inputs, presplit weights, projected q/k/v
__device__ __nv_bfloat16 g_xh[3*IN_N];
__device__ __nv_bfloat16 g_xl[3*IN_N];
__device__ __nv_bfloat16 g_wh[3*W_N];
__device__ __nv_bfloat16 g_wl[3*W_N];
__device__ __nv_bfloat16 g_ph[3*IN_N];
__device__ __nv_bfloat16 g_pl[3*IN_N];

// ===========================================================================
// Helpers (base PTX only — valid at compute_103)
// ===========================================================================
__device__ __forceinline__ uint32_t smem_u32(const void* p) {
    uint32_t a;
    asm("{ .reg .u64 t; cvta.to.shared.u64 t, %1; cvt.u32.u64 %0, t; }"
        : "=r"(a) : "l"(p));
    return a;
}
__device__ __forceinline__ void ldsm4(uint32_t* r, uint32_t addr) {
    asm volatile("ldmatrix.sync.aligned.m8n8.x4.shared.b16 {%0,%1,%2,%3}, [%4];"
                 : "=r"(r[0]), "=r"(r[1]), "=r"(r[2]), "=r"(r[3]) : "r"(addr));
}
__device__ __forceinline__ void ldsm4t(uint32_t* r, uint32_t addr) {
    asm volatile("ldmatrix.sync.aligned.m8n8.x4.trans.shared.b16 {%0,%1,%2,%3}, [%4];"
                 : "=r"(r[0]), "=r"(r[1]), "=r"(r[2]), "=r"(r[3]) : "r"(addr));
}
__device__ __forceinline__ void mma16816(float* d, const uint32_t* a, const uint32_t* b) {
    asm volatile("mma.sync.aligned.m16n8k16.row.col.f32.bf16.bf16.f32 "
                 "{%0,%1,%2,%3}, {%4,%5,%6,%7}, {%8,%9}, {%0,%1,%2,%3};"
                 : "+f"(d[0]), "+f"(d[1]), "+f"(d[2]), "+f"(d[3])
                 : "r"(a[0]), "r"(a[1]), "r"(a[2]), "r"(a[3]),
                   "r"(b[0]), "r"(b[1]));
}
__device__ __forceinline__ uint32_t swz(uint32_t bo) { return bo ^ ((bo >> 3) & 0x70); }
__device__ __forceinline__ float ex2(float x) {
    float r; asm("ex2.approx.f32 %0, %1;" : "=f"(r) : "f"(x)); return r;
}
__device__ __forceinline__ void split2(float x0, float x1, uint32_t& hi, uint32_t& lo) {
    __nv_bfloat162 h = __floats2bfloat162_rn(x0, x1);
    hi = *reinterpret_cast<uint32_t*>(&h);
    float r0 = x0 - __bfloat162float(h.x);
    float r1 = x1 - __bfloat162float(h.y);
    __nv_bfloat162 l = __floats2bfloat162_rn(r0, r1);
    lo = *reinterpret_cast<uint32_t*>(&l);
}
__device__ __forceinline__ uint32_t packbf(float lo, float hi) {
    __nv_bfloat162 h = __floats2bfloat162_rn(lo, hi);
    return *reinterpret_cast<uint32_t*>(&h);
}
__device__ __forceinline__ float ubf_lo(uint32_t p) { return __uint_as_float(p << 16); }
__device__ __forceinline__ float ubf_hi(uint32_t p) { return __uint_as_float(p & 0xFFFF0000u); }

#define CP16(dst, src) \
    asm volatile("cp.async.cg.shared.global [%0], [%1], 16;" :: "r"(dst), "l"(src))
#define CP_COMMIT() asm volatile("cp.async.commit_group;" ::: "memory")
#define CP_WAIT(n)  asm volatile("cp.async.wait_group %0;" :: "n"(n) : "memory")

// ===========================================================================
// Presplit: fp32 -> bf16 hi/lo planes (vectorized)
// ===========================================================================
__global__ void presplit_kernel(const float4* __restrict__ src,
                                uint2* __restrict__ dh, uint2* __restrict__ dl, int n4)
{
    int i = blockIdx.x * blockDim.x + threadIdx.x;
    if (i >= n4) return;
    float4 v = src[i];
    uint32_t h01, l01, h23, l23;
    split2(v.x, v.y, h01, l01);
    split2(v.z, v.w, h23, l23);
    dh[i] = make_uint2(h01, h23);
    dl[i] = make_uint2(l01, l23);
}

// ===========================================================================
// Projection GEMM on presplit bf16 planes, cp.async double-buffered.
// out_h/out_l planes [b,h,l,e], scale applied pre-split (QSCALE for Q).
// smem per stage: Ah 16K | Al 16K | Wh 16K | Wl 16K = 64KB; 2 stages = 128KB
// ===========================================================================
#define PROJ_SMEM 131072
#define PSTG 65536

__global__ __launch_bounds__(256, 1)
void mma_proj_kernel(const __nv_bfloat16* __restrict__ Ah, const __nv_bfloat16* __restrict__ Al,
                     const __nv_bfloat16* __restrict__ Wh, const __nv_bfloat16* __restrict__ Wl,
                     __nv_bfloat16* __restrict__ outh, __nv_bfloat16* __restrict__ outl,
                     float scale)
{
    extern __shared__ char smc[];
    const uint32_t sbase = smem_u32(smc);
    const int tid  = threadIdx.x;
    const int lane = tid & 31;
    const int wid  = tid >> 5;
    const int n0   = blockIdx.x * 128;
    const int m0   = blockIdx.y * 128;

    const int wm = (wid & 3) * 32;
    const int wn = (wid >> 2) * 64;

    float acc[2][8][4];
    #pragma unroll
    for (int mt = 0; mt < 2; mt++)
        #pragma unroll
        for (int nt = 0; nt < 8; nt++)
            #pragma unroll
            for (int r = 0; r < 4; r++) acc[mt][nt][r] = 0.f;

    const uint32_t a_row = wm + (lane & 15);
    const uint32_t a_kb0 = (lane >> 4) << 4;
    const uint32_t b_j   = lane >> 3;
    const uint32_t b_row = wn + (lane & 7) + ((b_j >> 1) << 3);
    const uint32_t b_kb0 = (b_j & 1) << 4;

    // loader: idx -> row r, 16B-chunk c16
    const int l_r   = tid >> 3;          // base rows 0..31 (advance by 32)
    const int l_c16 = tid & 7;

    // prologue: load chunk 0 -> stage 0
    {
        const int k0 = 0;
        #pragma unroll
        for (int j = 0; j < 4; ++j) {
            int r = l_r + j * 32;
            uint32_t dst = sbase + swz(r * 128 + l_c16 * 16);
            size_t ao = (size_t)(m0 + r) * DMODEL + k0 + l_c16 * 8;
            size_t wo = (size_t)(n0 + r) * DMODEL + k0 + l_c16 * 8;
            CP16(dst +     0, Ah + ao);
            CP16(dst + 16384, Al + ao);
            CP16(dst + 32768, Wh + wo);
            CP16(dst + 49152, Wl + wo);
        }
        CP_COMMIT();
    }

    for (int c = 0; c < 16; ++c) {
        if (c + 1 < 16) {
            const int k0 = (c + 1) * 64;
            const uint32_t stb = sbase + ((c + 1) & 1) * PSTG;
            #pragma unroll
            for (int j = 0; j < 4; ++j) {
                int r = l_r + j * 32;
                uint32_t dst = stb + swz(r * 128 + l_c16 * 16);
                size_t ao = (size_t)(m0 + r) * DMODEL + k0 + l_c16 * 8;
                size_t wo = (size_t)(n0 + r) * DMODEL + k0 + l_c16 * 8;
                CP16(dst +     0, Ah + ao);
                CP16(dst + 16384, Al + ao);
                CP16(dst + 32768, Wh + wo);
                CP16(dst + 49152, Wl + wo);
            }
            CP_COMMIT();
            CP_WAIT(1);
        } else {
            CP_WAIT(0);
        }
        __syncthreads();

        const uint32_t sst = sbase + (c & 1) * PSTG;
        #pragma unroll
        for (int kk = 0; kk < 4; ++kk) {
            const uint32_t kb = kk * 32;

            uint32_t ah[2][4], al[2][4];
            #pragma unroll
            for (int mt = 0; mt < 2; mt++) {
                uint32_t bo = (a_row + mt * 16) * 128 + kb + a_kb0;
                ldsm4(ah[mt], sst +     0 + swz(bo));
                ldsm4(al[mt], sst + 16384 + swz(bo));
            }
            uint32_t bh[8][2], bl[8][2];
            #pragma unroll
            for (int np = 0; np < 4; np++) {
                uint32_t bo = (b_row + np * 16) * 128 + kb + b_kb0;
                uint32_t t[4];
                ldsm4(t, sst + 32768 + swz(bo));
                bh[np*2+0][0] = t[0]; bh[np*2+0][1] = t[1];
                bh[np*2+1][0] = t[2]; bh[np*2+1][1] = t[3];
                ldsm4(t, sst + 49152 + swz(bo));
                bl[np*2+0][0] = t[0]; bl[np*2+0][1] = t[1];
                bl[np*2+1][0] = t[2]; bl[np*2+1][1] = t[3];
            }
            #pragma unroll
            for (int mt = 0; mt < 2; mt++)
                #pragma unroll
                for (int nt = 0; nt < 8; nt++) {
                    mma16816(acc[mt][nt], ah[mt], bh[nt]);
                    mma16816(acc[mt][nt], al[mt], bh[nt]);
                    mma16816(acc[mt][nt], ah[mt], bl[nt]);
                }
        }
        __syncthreads();
    }

    // epilogue: scale, split to bf16 hi/lo, write planes at [b,h,l,e]
    const int gid = lane >> 2;
    const int qid = lane & 3;
    #pragma unroll
    for (int mt = 0; mt < 2; mt++) {
        int m  = m0 + wm + mt * 16 + gid;
        int bb = m >> 10;
        int l  = m & 1023;
        #pragma unroll
        for (int nt = 0; nt < 8; nt++) {
            int n = n0 + wn + nt * 8 + qid * 2;
            int hh = n >> 6;
            int e  = n & 63;
            size_t idx0 = (((size_t)(bb * HEADS + hh) * SEQ + l) * DEPTH + e);
            size_t idx1 = idx0 + 8 * DEPTH;
            uint32_t hi, lo;
            split2(acc[mt][nt][0] * scale, acc[mt][nt][1] * scale, hi, lo);
            *(uint32_t*)(outh + idx0) = hi;
            *(uint32_t*)(outl + idx0) = lo;
            split2(acc[mt][nt][2] * scale, acc[mt][nt][3] * scale, hi, lo);
            *(uint32_t*)(outh + idx1) = hi;
            *(uint32_t*)(outl + idx1) = lo;
        }
    }
}

// ===========================================================================
// Flash attention on presplit bf16 planes, cp.async double-buffered KV.
// CTA: 128 q rows, 8 warps. KV tiles of 64.
// smem: KV stage0 32K | KV stage1 32K | Qh 16K | Ql 16K = 96KB
//   per KV stage: Kh@0 Kl@8192 Vh@16384 Vl@24576
// ===========================================================================
#define ATTN_SMEM 98304
#define KSTG 32768
#define AQH  65536
#define AQL  81920

__global__ __launch_bounds__(256)
void mma_attn_kernel(float* __restrict__ out,
                     const __nv_bfloat16* __restrict__ Qh, const __nv_bfloat16* __restrict__ Ql,
                     const __nv_bfloat16* __restrict__ Kh, const __nv_bfloat16* __restrict__ Kl,
                     const __nv_bfloat16* __restrict__ Vh, const __nv_bfloat16* __restrict__ Vl)
{
    extern __shared__ char smc[];
    const uint32_t sb = smem_u32(smc);
    const int tid  = threadIdx.x;
    const int lane = tid & 31;
    const int wid  = tid >> 5;
    const int qt   = blockIdx.x;
    const int h    = blockIdx.y;
    const int b    = blockIdx.z;

    const size_t base = (size_t)(b * HEADS + h) * SEQ * DEPTH;
    const __nv_bfloat16* qhp = Qh + base + (size_t)(qt * 128) * DEPTH;
    const __nv_bfloat16* qlp = Ql + base + (size_t)(qt * 128) * DEPTH;
    const __nv_bfloat16* khp = Kh + base;
    const __nv_bfloat16* klp = Kl + base;
    const __nv_bfloat16* vhp = Vh + base;
    const __nv_bfloat16* vlp = Vl + base;

    const int l_r   = tid >> 3;     // rows 0..31 base
    const int l_c16 = tid & 7;

    // prologue: Q (both planes) + KV tile 0 in one group
    {
        #pragma unroll
        for (int j = 0; j < 4; ++j) {
            int r = l_r + j * 32;
            uint32_t dst = sb + swz(r * 128 + l_c16 * 16);
            size_t qo = (size_t)r * DEPTH + l_c16 * 8;
            CP16(dst + AQH, qhp + qo);
            CP16(dst + AQL, qlp + qo);
        }
        #pragma unroll
        for (int j = 0; j < 2; ++j) {
            int r = l_r + j * 32;
            uint32_t dst = sb + swz(r * 128 + l_c16 * 16);
            size_t so = (size_t)r * DEPTH + l_c16 * 8;
            CP16(dst +     0, khp + so);
            CP16(dst +  8192, klp + so);
            CP16(dst + 16384, vhp + so);
            CP16(dst + 24576, vlp + so);
        }
        CP_COMMIT();
    }

    const int wm = wid * 16;
    const uint32_t qa_row = wm + (lane & 15);
    const uint32_t qa_cb  = (lane >> 4) << 4;
    const uint32_t kb_row = (lane & 7) + (((lane >> 4) & 1) << 3);
    const uint32_t kb_cb  = ((lane >> 3) & 1) << 4;
    const uint32_t va_row = (((lane >> 3) & 1) << 3) + (lane & 7);
    const uint32_t va_cb  = (lane >> 4) << 4;

    float m0 = -1e30f, m1 = -1e30f, l0 = 0.f, l1 = 0.f;
    float o[8][4];
    #pragma unroll
    for (int j = 0; j < 8; j++)
        #pragma unroll
        for (int r = 0; r < 4; r++) o[j][r] = 0.f;

    for (int t = 0; t < 16; ++t) {
        if (t + 1 < 16) {
            const uint32_t stb = sb + ((t + 1) & 1) * KSTG;
            #pragma unroll
            for (int j = 0; j < 2; ++j) {
                int r = l_r + j * 32;
                uint32_t dst = stb + swz(r * 128 + l_c16 * 16);
                size_t so = (size_t)((t + 1) * 64 + r) * DEPTH + l_c16 * 8;
                CP16(dst +     0, khp + so);
                CP16(dst +  8192, klp + so);
                CP16(dst + 16384, vhp + so);
                CP16(dst + 24576, vlp + so);
            }
            CP_COMMIT();
            CP_WAIT(1);
        } else {
            CP_WAIT(0);
        }
        __syncthreads();

        const uint32_t st = sb + (t & 1) * KSTG;

        // ---- S = Q Kt (3 split passes) ----
        float s[8][4];
        #pragma unroll
        for (int j = 0; j < 8; j++)
            #pragma unroll
            for (int r = 0; r < 4; r++) s[j][r] = 0.f;

        #pragma unroll
        for (int kk = 0; kk < 4; ++kk) {
            uint32_t qh[4], ql[4];
            uint32_t qoff = qa_row * 128 + kk * 32 + qa_cb;
            ldsm4(qh, sb + AQH + swz(qoff));
            ldsm4(ql, sb + AQL + swz(qoff));
            #pragma unroll
            for (int np = 0; np < 4; ++np) {
                uint32_t koff = (np * 16 + kb_row) * 128 + kk * 32 + kb_cb;
                uint32_t th[4], tl[4];
                ldsm4(th, st +    0 + swz(koff));
                ldsm4(tl, st + 8192 + swz(koff));
                mma16816(s[np*2+0], qh, th + 0);
                mma16816(s[np*2+0], ql, th + 0);
                mma16816(s[np*2+0], qh, tl + 0);
                mma16816(s[np*2+1], qh, th + 2);
                mma16816(s[np*2+1], ql, th + 2);
                mma16816(s[np*2+1], qh, tl + 2);
            }
        }

        // ---- online softmax (log2 domain) ----
        float mx0 = s[0][0], mx1 = s[0][2];
        #pragma unroll
        for (int j = 0; j < 8; j++) {
            mx0 = fmaxf(mx0, fmaxf(s[j][0], s[j][1]));
            mx1 = fmaxf(mx1, fmaxf(s[j][2], s[j][3]));
        }
        mx0 = fmaxf(mx0, __shfl_xor_sync(0xffffffffu, mx0, 1));
        mx0 = fmaxf(mx0, __shfl_xor_sync(0xffffffffu, mx0, 2));
        mx1 = fmaxf(mx1, __shfl_xor_sync(0xffffffffu, mx1, 1));
        mx1 = fmaxf(mx1, __shfl_xor_sync(0xffffffffu, mx1, 2));

        float mn0 = fmaxf(m0, mx0), mn1 = fmaxf(m1, mx1);
        float sc0 = ex2(m0 - mn0),  sc1 = ex2(m1 - mn1);
        m0 = mn0; m1 = mn1;

        float rs0 = 0.f, rs1 = 0.f;
        uint32_t ph[8][2], pl[8][2];
        #pragma unroll
        for (int j = 0; j < 8; j++) {
            float p0 = ex2(s[j][0] - m0);
            float p1 = ex2(s[j][1] - m0);
            float p2 = ex2(s[j][2] - m1);
            float p3 = ex2(s[j][3] - m1);
            rs0 += p0 + p1;
            rs1 += p2 + p3;
            ph[j][0] = packbf(p0, p1);
            ph[j][1] = packbf(p2, p3);
            pl[j][0] = packbf(p0 - ubf_lo(ph[j][0]), p1 - ubf_hi(ph[j][0]));
            pl[j][1] = packbf(p2 - ubf_lo(ph[j][1]), p3 - ubf_hi(ph[j][1]));
        }
        rs0 += __shfl_xor_sync(0xffffffffu, rs0, 1);
        rs0 += __shfl_xor_sync(0xffffffffu, rs0, 2);
        rs1 += __shfl_xor_sync(0xffffffffu, rs1, 1);
        rs1 += __shfl_xor_sync(0xffffffffu, rs1, 2);
        l0 = l0 * sc0 + rs0;
        l1 = l1 * sc1 + rs1;
        #pragma unroll
        for (int j = 0; j < 8; j++) {
            o[j][0] *= sc0; o[j][1] *= sc0;
            o[j][2] *= sc1; o[j][3] *= sc1;
        }

        // ---- O += P V (3 split passes), V via trans ldmatrix ----
        #pragma unroll
        for (int ks = 0; ks < 4; ++ks) {
            uint32_t ah[4] = { ph[ks*2][0], ph[ks*2][1], ph[ks*2+1][0], ph[ks*2+1][1] };
            uint32_t al[4] = { pl[ks*2][0], pl[ks*2][1], pl[ks*2+1][0], pl[ks*2+1][1] };
            #pragma unroll
            for (int dg = 0; dg < 4; ++dg) {
                uint32_t voff = (ks * 16 + va_row) * 128 + dg * 32 + va_cb;
                uint32_t th[4], tl[4];
                ldsm4t(th, st + 16384 + swz(voff));
                ldsm4t(tl, st + 24576 + swz(voff));
                mma16816(o[dg*2+0], ah, th + 0);
                mma16816(o[dg*2+0], al, th + 0);
                mma16816(o[dg*2+0], ah, tl + 0);
                mma16816(o[dg*2+1], ah, th + 2);
                mma16816(o[dg*2+1], al, th + 2);
                mma16816(o[dg*2+1], ah, tl + 2);
            }
        }
        __syncthreads();
    }

    // ---- epilogue: normalize, store to [B, L, H*DEPTH] ----
    float inv0 = 1.f / l0, inv1 = 1.f / l1;
    int r0 = qt * 128 + wm + (lane >> 2);
    float* p0 = out + ((size_t)b * SEQ + r0) * (HEADS * DEPTH) + h * DEPTH + (lane & 3) * 2;
    float* p1 = p0 + 8 * (HEADS * DEPTH);
    #pragma unroll
    for (int j = 0; j < 8; j++) {
        *(float2*)(p0 + j * 8) = make_float2(o[j][0] * inv0, o[j][1] * inv0);
        *(float2*)(p1 + j * 8) = make_float2(o[j][2] * inv1, o[j][3] * inv1);
    }
}

// ===========================================================================
extern "C" void kernel_launch(void* const* d_in, const int* in_sizes, int n_in,
                              void* d_out, int out_size)
{
    const float* query  = (const float*)d_in[0];
    const float* keys   = (const float*)d_in[1];
    const float* values = (const float*)d_in[2];
    const float* Wq     = (const float*)d_in[3];
    const float* Wk     = (const float*)d_in[4];
    const float* Wv     = (const float*)d_in[5];
    float* out = (float*)d_out;

    __nv_bfloat16 *xh, *xl, *wh, *wl, *ph, *pl;
    cudaGetSymbolAddress((void**)&xh, g_xh);
    cudaGetSymbolAddress((void**)&xl, g_xl);
    cudaGetSymbolAddress((void**)&wh, g_wh);
    cudaGetSymbolAddress((void**)&wl, g_wl);
    cudaGetSymbolAddress((void**)&ph, g_ph);
    cudaGetSymbolAddress((void**)&pl, g_pl);

    cudaFuncSetAttribute(mma_proj_kernel,
                         cudaFuncAttributeMaxDynamicSharedMemorySize, PROJ_SMEM);
    cudaFuncSetAttribute(mma_attn_kernel,
                         cudaFuncAttributeMaxDynamicSharedMemorySize, ATTN_SMEM);

    // presplit inputs (n4 = IN_N/4 = 2097152) and weights (n4 = W_N/4 = 262144)
    const float* xs[3] = {query, keys, values};
    const float* ws[3] = {Wq, Wk, Wv};
    for (int i = 0; i < 3; i++) {
        presplit_kernel<<<IN_N/4/256, 256>>>((const float4*)xs[i],
            (uint2*)(xh + (size_t)i*IN_N), (uint2*)(xl + (size_t)i*IN_N), IN_N/4);
        presplit_kernel<<<W_N/4/256, 256>>>((const float4*)ws[i],
            (uint2*)(wh + (size_t)i*W_N), (uint2*)(wl + (size_t)i*W_N), W_N/4);
    }

    dim3 pgrid(DMODEL / 128, (BATCH * SEQ) / 128);   // (8, 64)
    const float scales[3] = {QSCALE, 1.0f, 1.0f};
    for (int i = 0; i < 3; i++) {
        mma_proj_kernel<<<pgrid, 256, PROJ_SMEM>>>(
            xh + (size_t)i*IN_N, xl + (size_t)i*IN_N,
            wh + (size_t)i*W_N,  wl + (size_t)i*W_N,
            ph + (size_t)i*IN_N, pl + (size_t)i*IN_N, scales[i]);
    }

    dim3 agrid(SEQ / 128, HEADS, BATCH);             // (8, 16, 8)
    mma_attn_kernel<<<agrid, 256, ATTN_SMEM>>>(out,
        ph + 0,              pl + 0,
        ph + (size_t)IN_N,   pl + (size_t)IN_N,
        ph + (size_t)2*IN_N, pl + (size_t)2*IN_N);
}

// round 6
// speedup vs baseline: 4.4092x; 1.1170x over previous
#include <cuda_runtime.h>
#include <cuda_bf16.h>
#include <cstdint>

#define BATCH  8
#define HEADS  16
#define SEQ    1024
#define DMODEL 1024
#define DEPTH  64

#define IN_N   (BATCH*SEQ*DMODEL)      // 8388608  (== BATCH*HEADS*SEQ*DEPTH)
#define W_N    (DMODEL*DMODEL)         // 1048576
#define QSCALE 0.18033688f             /* 0.125 * log2(e) */

// bf16 hi/lo planes: presplit inputs, presplit weights, projected q/k/v
__device__ __nv_bfloat16 g_xh[3*IN_N];
__device__ __nv_bfloat16 g_xl[3*IN_N];
__device__ __nv_bfloat16 g_wh[3*W_N];
__device__ __nv_bfloat16 g_wl[3*W_N];
__device__ __nv_bfloat16 g_ph[3*IN_N];
__device__ __nv_bfloat16 g_pl[3*IN_N];

// ===========================================================================
// Helpers (base PTX only — valid at compute_103)
// ===========================================================================
__device__ __forceinline__ uint32_t smem_u32(const void* p) {
    uint32_t a;
    asm("{ .reg .u64 t; cvta.to.shared.u64 t, %1; cvt.u32.u64 %0, t; }"
        : "=r"(a) : "l"(p));
    return a;
}
__device__ __forceinline__ void ldsm4(uint32_t* r, uint32_t addr) {
    asm volatile("ldmatrix.sync.aligned.m8n8.x4.shared.b16 {%0,%1,%2,%3}, [%4];"
                 : "=r"(r[0]), "=r"(r[1]), "=r"(r[2]), "=r"(r[3]) : "r"(addr));
}
__device__ __forceinline__ void ldsm4t(uint32_t* r, uint32_t addr) {
    asm volatile("ldmatrix.sync.aligned.m8n8.x4.trans.shared.b16 {%0,%1,%2,%3}, [%4];"
                 : "=r"(r[0]), "=r"(r[1]), "=r"(r[2]), "=r"(r[3]) : "r"(addr));
}
__device__ __forceinline__ void mma16816(float* d, const uint32_t* a, const uint32_t* b) {
    asm volatile("mma.sync.aligned.m16n8k16.row.col.f32.bf16.bf16.f32 "
                 "{%0,%1,%2,%3}, {%4,%5,%6,%7}, {%8,%9}, {%0,%1,%2,%3};"
                 : "+f"(d[0]), "+f"(d[1]), "+f"(d[2]), "+f"(d[3])
                 : "r"(a[0]), "r"(a[1]), "r"(a[2]), "r"(a[3]),
                   "r"(b[0]), "r"(b[1]));
}
__device__ __forceinline__ uint32_t swz(uint32_t bo) { return bo ^ ((bo >> 3) & 0x70); }
__device__ __forceinline__ float ex2(float x) {
    float r; asm("ex2.approx.f32 %0, %1;" : "=f"(r) : "f"(x)); return r;
}
__device__ __forceinline__ void split2(float x0, float x1, uint32_t& hi, uint32_t& lo) {
    __nv_bfloat162 h = __floats2bfloat162_rn(x0, x1);
    hi = *reinterpret_cast<uint32_t*>(&h);
    float r0 = x0 - __bfloat162float(h.x);
    float r1 = x1 - __bfloat162float(h.y);
    __nv_bfloat162 l = __floats2bfloat162_rn(r0, r1);
    lo = *reinterpret_cast<uint32_t*>(&l);
}
__device__ __forceinline__ uint32_t packbf(float lo, float hi) {
    __nv_bfloat162 h = __floats2bfloat162_rn(lo, hi);
    return *reinterpret_cast<uint32_t*>(&h);
}
__device__ __forceinline__ float ubf_lo(uint32_t p) { return __uint_as_float(p << 16); }
__device__ __forceinline__ float ubf_hi(uint32_t p) { return __uint_as_float(p & 0xFFFF0000u); }

#define CP16(dst, src) \
    asm volatile("cp.async.cg.shared.global [%0], [%1], 16;" :: "r"(dst), "l"(src))
#define CP_COMMIT() asm volatile("cp.async.commit_group;" ::: "memory")
#define CP_WAIT(n)  asm volatile("cp.async.wait_group %0;" :: "n"(n) : "memory")

// ===========================================================================
// Presplit: fp32 -> bf16 hi/lo planes; z dimension picks source array
// ===========================================================================
__global__ void presplit3_kernel(const float4* __restrict__ s0,
                                 const float4* __restrict__ s1,
                                 const float4* __restrict__ s2,
                                 uint2* __restrict__ dh, uint2* __restrict__ dl,
                                 int n4)
{
    int i = blockIdx.x * blockDim.x + threadIdx.x;
    if (i >= n4) return;
    int z = blockIdx.y;
    const float4* src = (z == 0) ? s0 : (z == 1) ? s1 : s2;
    float4 v = src[i];
    uint32_t h01, l01, h23, l23;
    split2(v.x, v.y, h01, l01);
    split2(v.z, v.w, h23, l23);
    dh[(size_t)z * n4 + i] = make_uint2(h01, h23);
    dl[(size_t)z * n4 + i] = make_uint2(l01, l23);
}

// ===========================================================================
// Projection GEMM on presplit bf16 planes, cp.async double-buffered.
// grid.z = 0(Q)/1(K)/2(V). Writes bf16 hi/lo planes, Q pre-scaled by QSCALE.
// smem per stage: Ah 16K | Al 16K | Wh 16K | Wl 16K = 64KB; 2 stages = 128KB
// ===========================================================================
#define PROJ_SMEM 131072
#define PSTG 65536

__global__ __launch_bounds__(256, 1)
void mma_proj_kernel(const __nv_bfloat16* __restrict__ AhG, const __nv_bfloat16* __restrict__ AlG,
                     const __nv_bfloat16* __restrict__ WhG, const __nv_bfloat16* __restrict__ WlG,
                     __nv_bfloat16* __restrict__ outhG, __nv_bfloat16* __restrict__ outlG)
{
    extern __shared__ char smc[];
    const uint32_t sbase = smem_u32(smc);
    const int tid  = threadIdx.x;
    const int lane = tid & 31;
    const int wid  = tid >> 5;
    const int n0   = blockIdx.x * 128;
    const int m0   = blockIdx.y * 128;
    const int z    = blockIdx.z;

    const __nv_bfloat16* Ah = AhG + (size_t)z * IN_N;
    const __nv_bfloat16* Al = AlG + (size_t)z * IN_N;
    const __nv_bfloat16* Wh = WhG + (size_t)z * W_N;
    const __nv_bfloat16* Wl = WlG + (size_t)z * W_N;
    __nv_bfloat16* outh = outhG + (size_t)z * IN_N;
    __nv_bfloat16* outl = outlG + (size_t)z * IN_N;
    const float scale = (z == 0) ? QSCALE : 1.0f;

    const int wm = (wid & 3) * 32;
    const int wn = (wid >> 2) * 64;

    float acc[2][8][4];
    #pragma unroll
    for (int mt = 0; mt < 2; mt++)
        #pragma unroll
        for (int nt = 0; nt < 8; nt++)
            #pragma unroll
            for (int r = 0; r < 4; r++) acc[mt][nt][r] = 0.f;

    const uint32_t a_row = wm + (lane & 15);
    const uint32_t a_kb0 = (lane >> 4) << 4;
    const uint32_t b_j   = lane >> 3;
    const uint32_t b_row = wn + (lane & 7) + ((b_j >> 1) << 3);
    const uint32_t b_kb0 = (b_j & 1) << 4;

    const int l_r   = tid >> 3;
    const int l_c16 = tid & 7;

    // prologue: chunk 0 -> stage 0
    {
        #pragma unroll
        for (int j = 0; j < 4; ++j) {
            int r = l_r + j * 32;
            uint32_t dst = sbase + swz(r * 128 + l_c16 * 16);
            size_t ao = (size_t)(m0 + r) * DMODEL + l_c16 * 8;
            size_t wo = (size_t)(n0 + r) * DMODEL + l_c16 * 8;
            CP16(dst +     0, Ah + ao);
            CP16(dst + 16384, Al + ao);
            CP16(dst + 32768, Wh + wo);
            CP16(dst + 49152, Wl + wo);
        }
        CP_COMMIT();
    }

    for (int c = 0; c < 16; ++c) {
        if (c + 1 < 16) {
            const int k0 = (c + 1) * 64;
            const uint32_t stb = sbase + ((c + 1) & 1) * PSTG;
            #pragma unroll
            for (int j = 0; j < 4; ++j) {
                int r = l_r + j * 32;
                uint32_t dst = stb + swz(r * 128 + l_c16 * 16);
                size_t ao = (size_t)(m0 + r) * DMODEL + k0 + l_c16 * 8;
                size_t wo = (size_t)(n0 + r) * DMODEL + k0 + l_c16 * 8;
                CP16(dst +     0, Ah + ao);
                CP16(dst + 16384, Al + ao);
                CP16(dst + 32768, Wh + wo);
                CP16(dst + 49152, Wl + wo);
            }
            CP_COMMIT();
            CP_WAIT(1);
        } else {
            CP_WAIT(0);
        }
        __syncthreads();

        const uint32_t sst = sbase + (c & 1) * PSTG;
        #pragma unroll
        for (int kk = 0; kk < 4; ++kk) {
            const uint32_t kb = kk * 32;

            uint32_t ah[2][4], al[2][4];
            #pragma unroll
            for (int mt = 0; mt < 2; mt++) {
                uint32_t bo = (a_row + mt * 16) * 128 + kb + a_kb0;
                ldsm4(ah[mt], sst +     0 + swz(bo));
                ldsm4(al[mt], sst + 16384 + swz(bo));
            }
            uint32_t bh[8][2], bl[8][2];
            #pragma unroll
            for (int np = 0; np < 4; np++) {
                uint32_t bo = (b_row + np * 16) * 128 + kb + b_kb0;
                uint32_t t[4];
                ldsm4(t, sst + 32768 + swz(bo));
                bh[np*2+0][0] = t[0]; bh[np*2+0][1] = t[1];
                bh[np*2+1][0] = t[2]; bh[np*2+1][1] = t[3];
                ldsm4(t, sst + 49152 + swz(bo));
                bl[np*2+0][0] = t[0]; bl[np*2+0][1] = t[1];
                bl[np*2+1][0] = t[2]; bl[np*2+1][1] = t[3];
            }
            #pragma unroll
            for (int mt = 0; mt < 2; mt++)
                #pragma unroll
                for (int nt = 0; nt < 8; nt++) {
                    mma16816(acc[mt][nt], ah[mt], bh[nt]);
                    mma16816(acc[mt][nt], al[mt], bh[nt]);
                    mma16816(acc[mt][nt], ah[mt], bl[nt]);
                }
        }
        __syncthreads();
    }

    // epilogue: scale, split to bf16 hi/lo planes at [b,h,l,e]
    const int gid = lane >> 2;
    const int qid = lane & 3;
    #pragma unroll
    for (int mt = 0; mt < 2; mt++) {
        int m  = m0 + wm + mt * 16 + gid;
        int bb = m >> 10;
        int l  = m & 1023;
        #pragma unroll
        for (int nt = 0; nt < 8; nt++) {
            int n = n0 + wn + nt * 8 + qid * 2;
            int hh = n >> 6;
            int e  = n & 63;
            size_t idx0 = (((size_t)(bb * HEADS + hh) * SEQ + l) * DEPTH + e);
            size_t idx1 = idx0 + 8 * DEPTH;
            uint32_t hi, lo;
            split2(acc[mt][nt][0] * scale, acc[mt][nt][1] * scale, hi, lo);
            *(uint32_t*)(outh + idx0) = hi;
            *(uint32_t*)(outl + idx0) = lo;
            split2(acc[mt][nt][2] * scale, acc[mt][nt][3] * scale, hi, lo);
            *(uint32_t*)(outh + idx1) = hi;
            *(uint32_t*)(outl + idx1) = lo;
        }
    }
}

// ===========================================================================
// Flash attention: 4 warps, 64 q rows/CTA, Q fragments hoisted to registers,
// KV double-buffered via cp.async. Target 2 CTAs/SM.
// smem: KV stage0 32K | KV stage1 32K | Q 16K = 80KB
//   per KV stage: Kh@0 Kl@8192 Vh@16384 Vl@24576 ; Q: hi@65536 lo@73728
// ===========================================================================
#define ATTN_SMEM 81920
#define KSTG 32768
#define AQH  65536
#define AQL  73728

__global__ __launch_bounds__(128, 2)
void mma_attn_kernel(float* __restrict__ out,
                     const __nv_bfloat16* __restrict__ Qh, const __nv_bfloat16* __restrict__ Ql,
                     const __nv_bfloat16* __restrict__ Kh, const __nv_bfloat16* __restrict__ Kl,
                     const __nv_bfloat16* __restrict__ Vh, const __nv_bfloat16* __restrict__ Vl)
{
    extern __shared__ char smc[];
    const uint32_t sb = smem_u32(smc);
    const int tid  = threadIdx.x;
    const int lane = tid & 31;
    const int wid  = tid >> 5;
    const int qt   = blockIdx.x;
    const int h    = blockIdx.y;
    const int b    = blockIdx.z;

    const size_t base = (size_t)(b * HEADS + h) * SEQ * DEPTH;
    const __nv_bfloat16* qhp = Qh + base + (size_t)(qt * 64) * DEPTH;
    const __nv_bfloat16* qlp = Ql + base + (size_t)(qt * 64) * DEPTH;
    const __nv_bfloat16* khp = Kh + base;
    const __nv_bfloat16* klp = Kl + base;
    const __nv_bfloat16* vhp = Vh + base;
    const __nv_bfloat16* vlp = Vl + base;

    const int l_r   = tid >> 3;     // rows 0..15 base (advance by 16)
    const int l_c16 = tid & 7;

    // prologue: Q planes + KV tile 0
    {
        #pragma unroll
        for (int j = 0; j < 4; ++j) {
            int r = l_r + j * 16;
            uint32_t dst = sb + swz(r * 128 + l_c16 * 16);
            size_t qo = (size_t)r * DEPTH + l_c16 * 8;
            CP16(dst + AQH, qhp + qo);
            CP16(dst + AQL, qlp + qo);
        }
        #pragma unroll
        for (int j = 0; j < 4; ++j) {
            int r = l_r + j * 16;
            uint32_t dst = sb + swz(r * 128 + l_c16 * 16);
            size_t so = (size_t)r * DEPTH + l_c16 * 8;
            CP16(dst +     0, khp + so);
            CP16(dst +  8192, klp + so);
            CP16(dst + 16384, vhp + so);
            CP16(dst + 24576, vlp + so);
        }
        CP_COMMIT();
        CP_WAIT(0);
    }
    __syncthreads();

    const int wm = wid * 16;
    const uint32_t qa_row = wm + (lane & 15);
    const uint32_t qa_cb  = (lane >> 4) << 4;
    const uint32_t kb_row = (lane & 7) + (((lane >> 4) & 1) << 3);
    const uint32_t kb_cb  = ((lane >> 3) & 1) << 4;
    const uint32_t va_row = (((lane >> 3) & 1) << 3) + (lane & 7);
    const uint32_t va_cb  = (lane >> 4) << 4;

    // hoist Q fragments into registers (Q smem then idle)
    uint32_t qh[4][4], ql[4][4];
    #pragma unroll
    for (int kk = 0; kk < 4; ++kk) {
        uint32_t qoff = qa_row * 128 + kk * 32 + qa_cb;
        ldsm4(qh[kk], sb + AQH + swz(qoff));
        ldsm4(ql[kk], sb + AQL + swz(qoff));
    }

    float m0 = -1e30f, m1 = -1e30f, l0 = 0.f, l1 = 0.f;
    float o[8][4];
    #pragma unroll
    for (int j = 0; j < 8; j++)
        #pragma unroll
        for (int r = 0; r < 4; r++) o[j][r] = 0.f;

    for (int t = 0; t < 16; ++t) {
        if (t + 1 < 16) {
            const uint32_t stb = sb + ((t + 1) & 1) * KSTG;
            #pragma unroll
            for (int j = 0; j < 4; ++j) {
                int r = l_r + j * 16;
                uint32_t dst = stb + swz(r * 128 + l_c16 * 16);
                size_t so = (size_t)((t + 1) * 64 + r) * DEPTH + l_c16 * 8;
                CP16(dst +     0, khp + so);
                CP16(dst +  8192, klp + so);
                CP16(dst + 16384, vhp + so);
                CP16(dst + 24576, vlp + so);
            }
            CP_COMMIT();
            CP_WAIT(1);
        } else {
            CP_WAIT(0);
        }
        __syncthreads();

        const uint32_t st = sb + (t & 1) * KSTG;

        // ---- S = Q Kt (3 split passes) ----
        float s[8][4];
        #pragma unroll
        for (int j = 0; j < 8; j++)
            #pragma unroll
            for (int r = 0; r < 4; r++) s[j][r] = 0.f;

        #pragma unroll
        for (int kk = 0; kk < 4; ++kk) {
            #pragma unroll
            for (int np = 0; np < 4; ++np) {
                uint32_t koff = (np * 16 + kb_row) * 128 + kk * 32 + kb_cb;
                uint32_t th[4], tl[4];
                ldsm4(th, st +    0 + swz(koff));
                ldsm4(tl, st + 8192 + swz(koff));
                mma16816(s[np*2+0], qh[kk], th + 0);
                mma16816(s[np*2+0], ql[kk], th + 0);
                mma16816(s[np*2+0], qh[kk], tl + 0);
                mma16816(s[np*2+1], qh[kk], th + 2);
                mma16816(s[np*2+1], ql[kk], th + 2);
                mma16816(s[np*2+1], qh[kk], tl + 2);
            }
        }

        // ---- online softmax (log2 domain) ----
        float mx0 = s[0][0], mx1 = s[0][2];
        #pragma unroll
        for (int j = 0; j < 8; j++) {
            mx0 = fmaxf(mx0, fmaxf(s[j][0], s[j][1]));
            mx1 = fmaxf(mx1, fmaxf(s[j][2], s[j][3]));
        }
        mx0 = fmaxf(mx0, __shfl_xor_sync(0xffffffffu, mx0, 1));
        mx0 = fmaxf(mx0, __shfl_xor_sync(0xffffffffu, mx0, 2));
        mx1 = fmaxf(mx1, __shfl_xor_sync(0xffffffffu, mx1, 1));
        mx1 = fmaxf(mx1, __shfl_xor_sync(0xffffffffu, mx1, 2));

        float mn0 = fmaxf(m0, mx0), mn1 = fmaxf(m1, mx1);
        float sc0 = ex2(m0 - mn0),  sc1 = ex2(m1 - mn1);
        m0 = mn0; m1 = mn1;

        float rs0 = 0.f, rs1 = 0.f;
        uint32_t ph[8][2], pl[8][2];
        #pragma unroll
        for (int j = 0; j < 8; j++) {
            float p0 = ex2(s[j][0] - m0);
            float p1 = ex2(s[j][1] - m0);
            float p2 = ex2(s[j][2] - m1);
            float p3 = ex2(s[j][3] - m1);
            rs0 += p0 + p1;
            rs1 += p2 + p3;
            ph[j][0] = packbf(p0, p1);
            ph[j][1] = packbf(p2, p3);
            pl[j][0] = packbf(p0 - ubf_lo(ph[j][0]), p1 - ubf_hi(ph[j][0]));
            pl[j][1] = packbf(p2 - ubf_lo(ph[j][1]), p3 - ubf_hi(ph[j][1]));
        }
        rs0 += __shfl_xor_sync(0xffffffffu, rs0, 1);
        rs0 += __shfl_xor_sync(0xffffffffu, rs0, 2);
        rs1 += __shfl_xor_sync(0xffffffffu, rs1, 1);
        rs1 += __shfl_xor_sync(0xffffffffu, rs1, 2);
        l0 = l0 * sc0 + rs0;
        l1 = l1 * sc1 + rs1;
        #pragma unroll
        for (int j = 0; j < 8; j++) {
            o[j][0] *= sc0; o[j][1] *= sc0;
            o[j][2] *= sc1; o[j][3] *= sc1;
        }

        // ---- O += P V (3 split passes), V via trans ldmatrix ----
        #pragma unroll
        for (int ks = 0; ks < 4; ++ks) {
            uint32_t ah[4] = { ph[ks*2][0], ph[ks*2][1], ph[ks*2+1][0], ph[ks*2+1][1] };
            uint32_t al[4] = { pl[ks*2][0], pl[ks*2][1], pl[ks*2+1][0], pl[ks*2+1][1] };
            #pragma unroll
            for (int dg = 0; dg < 4; ++dg) {
                uint32_t voff = (ks * 16 + va_row) * 128 + dg * 32 + va_cb;
                uint32_t th[4], tl[4];
                ldsm4t(th, st + 16384 + swz(voff));
                ldsm4t(tl, st + 24576 + swz(voff));
                mma16816(o[dg*2+0], ah, th + 0);
                mma16816(o[dg*2+0], al, th + 0);
                mma16816(o[dg*2+0], ah, tl + 0);
                mma16816(o[dg*2+1], ah, th + 2);
                mma16816(o[dg*2+1], al, th + 2);
                mma16816(o[dg*2+1], ah, tl + 2);
            }
        }
        __syncthreads();
    }

    // ---- epilogue: normalize, store to [B, L, H*DEPTH] ----
    float inv0 = 1.f / l0, inv1 = 1.f / l1;
    int r0 = qt * 64 + wm + (lane >> 2);
    float* p0 = out + ((size_t)b * SEQ + r0) * (HEADS * DEPTH) + h * DEPTH + (lane & 3) * 2;
    float* p1 = p0 + 8 * (HEADS * DEPTH);
    #pragma unroll
    for (int j = 0; j < 8; j++) {
        *(float2*)(p0 + j * 8) = make_float2(o[j][0] * inv0, o[j][1] * inv0);
        *(float2*)(p1 + j * 8) = make_float2(o[j][2] * inv1, o[j][3] * inv1);
    }
}

// ===========================================================================
extern "C" void kernel_launch(void* const* d_in, const int* in_sizes, int n_in,
                              void* d_out, int out_size)
{
    const float* query  = (const float*)d_in[0];
    const float* keys   = (const float*)d_in[1];
    const float* values = (const float*)d_in[2];
    const float* Wq     = (const float*)d_in[3];
    const float* Wk     = (const float*)d_in[4];
    const float* Wv     = (const float*)d_in[5];
    float* out = (float*)d_out;

    __nv_bfloat16 *xh, *xl, *wh, *wl, *ph, *pl;
    cudaGetSymbolAddress((void**)&xh, g_xh);
    cudaGetSymbolAddress((void**)&xl, g_xl);
    cudaGetSymbolAddress((void**)&wh, g_wh);
    cudaGetSymbolAddress((void**)&wl, g_wl);
    cudaGetSymbolAddress((void**)&ph, g_ph);
    cudaGetSymbolAddress((void**)&pl, g_pl);

    cudaFuncSetAttribute(mma_proj_kernel,
                         cudaFuncAttributeMaxDynamicSharedMemorySize, PROJ_SMEM);
    cudaFuncSetAttribute(mma_attn_kernel,
                         cudaFuncAttributeMaxDynamicSharedMemorySize, ATTN_SMEM);

    // presplit: inputs (one launch) and weights (one launch)
    {
        dim3 g1(IN_N/4/256, 3);
        presplit3_kernel<<<g1, 256>>>((const float4*)query, (const float4*)keys,
                                      (const float4*)values,
                                      (uint2*)xh, (uint2*)xl, IN_N/4);
        dim3 g2(W_N/4/256, 3);
        presplit3_kernel<<<g2, 256>>>((const float4*)Wq, (const float4*)Wk,
                                      (const float4*)Wv,
                                      (uint2*)wh, (uint2*)wl, W_N/4);
    }

    dim3 pgrid(DMODEL / 128, (BATCH * SEQ) / 128, 3);   // (8, 64, 3)
    mma_proj_kernel<<<pgrid, 256, PROJ_SMEM>>>(xh, xl, wh, wl, ph, pl);

    dim3 agrid(SEQ / 64, HEADS, BATCH);                 // (16, 16, 8)
    mma_attn_kernel<<<agrid, 128, ATTN_SMEM>>>(out,
        ph + 0,              pl + 0,
        ph + (size_t)IN_N,   pl + (size_t)IN_N,
        ph + (size_t)2*IN_N, pl + (size_t)2*IN_N);
}

// round 7
// speedup vs baseline: 4.5530x; 1.0326x over previous
#include <cuda_runtime.h>
#include <cuda_bf16.h>
#include <cstdint>

#define BATCH  8
#define HEADS  16
#define SEQ    1024
#define DMODEL 1024
#define DEPTH  64

#define IN_N   (BATCH*SEQ*DMODEL)      // 8388608  (== BATCH*HEADS*SEQ*DEPTH)
#define W_N    (DMODEL*DMODEL)         // 1048576
#define QSCALE 0.18033688f             /* 0.125 * log2(e) */

// bf16 hi/lo planes: presplit inputs, presplit weights, projected q/k/v
__device__ __nv_bfloat16 g_xh[3*IN_N];
__device__ __nv_bfloat16 g_xl[3*IN_N];
__device__ __nv_bfloat16 g_wh[3*W_N];
__device__ __nv_bfloat16 g_wl[3*W_N];
__device__ __nv_bfloat16 g_ph[3*IN_N];
__device__ __nv_bfloat16 g_pl[3*IN_N];

// ===========================================================================
// Helpers (base PTX only — valid at compute_103)
// ===========================================================================
__device__ __forceinline__ uint32_t smem_u32(const void* p) {
    uint32_t a;
    asm("{ .reg .u64 t; cvta.to.shared.u64 t, %1; cvt.u32.u64 %0, t; }"
        : "=r"(a) : "l"(p));
    return a;
}
__device__ __forceinline__ void ldsm4(uint32_t* r, uint32_t addr) {
    asm volatile("ldmatrix.sync.aligned.m8n8.x4.shared.b16 {%0,%1,%2,%3}, [%4];"
                 : "=r"(r[0]), "=r"(r[1]), "=r"(r[2]), "=r"(r[3]) : "r"(addr));
}
__device__ __forceinline__ void ldsm4t(uint32_t* r, uint32_t addr) {
    asm volatile("ldmatrix.sync.aligned.m8n8.x4.trans.shared.b16 {%0,%1,%2,%3}, [%4];"
                 : "=r"(r[0]), "=r"(r[1]), "=r"(r[2]), "=r"(r[3]) : "r"(addr));
}
__device__ __forceinline__ void mma16816(float* d, const uint32_t* a, const uint32_t* b) {
    asm volatile("mma.sync.aligned.m16n8k16.row.col.f32.bf16.bf16.f32 "
                 "{%0,%1,%2,%3}, {%4,%5,%6,%7}, {%8,%9}, {%0,%1,%2,%3};"
                 : "+f"(d[0]), "+f"(d[1]), "+f"(d[2]), "+f"(d[3])
                 : "r"(a[0]), "r"(a[1]), "r"(a[2]), "r"(a[3]),
                   "r"(b[0]), "r"(b[1]));
}
__device__ __forceinline__ uint32_t swz(uint32_t bo) { return bo ^ ((bo >> 3) & 0x70); }
__device__ __forceinline__ float ex2(float x) {
    float r; asm("ex2.approx.f32 %0, %1;" : "=f"(r) : "f"(x)); return r;
}
__device__ __forceinline__ void split2(float x0, float x1, uint32_t& hi, uint32_t& lo) {
    __nv_bfloat162 h = __floats2bfloat162_rn(x0, x1);
    hi = *reinterpret_cast<uint32_t*>(&h);
    float r0 = x0 - __bfloat162float(h.x);
    float r1 = x1 - __bfloat162float(h.y);
    __nv_bfloat162 l = __floats2bfloat162_rn(r0, r1);
    lo = *reinterpret_cast<uint32_t*>(&l);
}
__device__ __forceinline__ uint32_t packbf(float lo, float hi) {
    __nv_bfloat162 h = __floats2bfloat162_rn(lo, hi);
    return *reinterpret_cast<uint32_t*>(&h);
}
__device__ __forceinline__ float ubf_lo(uint32_t p) { return __uint_as_float(p << 16); }
__device__ __forceinline__ float ubf_hi(uint32_t p) { return __uint_as_float(p & 0xFFFF0000u); }

#define CP16(dst, src) \
    asm volatile("cp.async.cg.shared.global [%0], [%1], 16;" :: "r"(dst), "l"(src))
#define CP_COMMIT() asm volatile("cp.async.commit_group;" ::: "memory")
#define CP_WAIT(n)  asm volatile("cp.async.wait_group %0;" :: "n"(n) : "memory")

// ===========================================================================
// Presplit: fp32 -> bf16 hi/lo planes; z dimension picks source array
// ===========================================================================
__global__ void presplit3_kernel(const float4* __restrict__ s0,
                                 const float4* __restrict__ s1,
                                 const float4* __restrict__ s2,
                                 uint2* __restrict__ dh, uint2* __restrict__ dl,
                                 int n4)
{
    int i = blockIdx.x * blockDim.x + threadIdx.x;
    if (i >= n4) return;
    int z = blockIdx.y;
    const float4* src = (z == 0) ? s0 : (z == 1) ? s1 : s2;
    float4 v = src[i];
    uint32_t h01, l01, h23, l23;
    split2(v.x, v.y, h01, l01);
    split2(v.z, v.w, h23, l23);
    dh[(size_t)z * n4 + i] = make_uint2(h01, h23);
    dl[(size_t)z * n4 + i] = make_uint2(l01, l23);
}

// ===========================================================================
// Projection GEMM on presplit bf16 planes, cp.async double-buffered.
// NEW: 128 threads, tile 64(M)x128(N), 2 CTAs/SM.
// grid.z = 0(Q)/1(K)/2(V). Writes bf16 hi/lo planes, Q pre-scaled by QSCALE.
// smem per stage: Ah 8K @0 | Al 8K @8192 | Wh 16K @16384 | Wl 16K @32768 = 48K
// 2 stages = 96KB -> 2 CTAs/SM.
// ===========================================================================
#define PSTG      49152
#define PROJ_SMEM (2*PSTG)
#define POA_H 0
#define POA_L 8192
#define POW_H 16384
#define POW_L 32768

__global__ __launch_bounds__(128, 2)
void mma_proj_kernel(const __nv_bfloat16* __restrict__ AhG, const __nv_bfloat16* __restrict__ AlG,
                     const __nv_bfloat16* __restrict__ WhG, const __nv_bfloat16* __restrict__ WlG,
                     __nv_bfloat16* __restrict__ outhG, __nv_bfloat16* __restrict__ outlG)
{
    extern __shared__ char smc[];
    const uint32_t sbase = smem_u32(smc);
    const int tid  = threadIdx.x;
    const int lane = tid & 31;
    const int wid  = tid >> 5;
    const int n0   = blockIdx.x * 128;
    const int m0   = blockIdx.y * 64;
    const int z    = blockIdx.z;

    const __nv_bfloat16* Ah = AhG + (size_t)z * IN_N;
    const __nv_bfloat16* Al = AlG + (size_t)z * IN_N;
    const __nv_bfloat16* Wh = WhG + (size_t)z * W_N;
    const __nv_bfloat16* Wl = WlG + (size_t)z * W_N;
    __nv_bfloat16* outh = outhG + (size_t)z * IN_N;
    __nv_bfloat16* outl = outlG + (size_t)z * IN_N;
    const float scale = (z == 0) ? QSCALE : 1.0f;

    const int wm = (wid & 1) * 32;     // warp M offset (tile M=64)
    const int wn = (wid >> 1) * 64;    // warp N offset (tile N=128)

    float acc[2][8][4];
    #pragma unroll
    for (int mt = 0; mt < 2; mt++)
        #pragma unroll
        for (int nt = 0; nt < 8; nt++)
            #pragma unroll
            for (int r = 0; r < 4; r++) acc[mt][nt][r] = 0.f;

    const uint32_t a_row = wm + (lane & 15);
    const uint32_t a_kb0 = (lane >> 4) << 4;
    const uint32_t b_j   = lane >> 3;
    const uint32_t b_row = wn + (lane & 7) + ((b_j >> 1) << 3);
    const uint32_t b_kb0 = (b_j & 1) << 4;

    const int l_r   = tid >> 3;        // 0..15, rows advance by 16
    const int l_c16 = tid & 7;

    // prologue: chunk 0 -> stage 0
    {
        #pragma unroll
        for (int j = 0; j < 4; ++j) {               // A: 64 rows
            int r = l_r + j * 16;
            uint32_t dst = sbase + swz(r * 128 + l_c16 * 16);
            size_t ao = (size_t)(m0 + r) * DMODEL + l_c16 * 8;
            CP16(dst + POA_H, Ah + ao);
            CP16(dst + POA_L, Al + ao);
        }
        #pragma unroll
        for (int j = 0; j < 8; ++j) {               // W: 128 rows
            int r = l_r + j * 16;
            uint32_t dst = sbase + swz(r * 128 + l_c16 * 16);
            size_t wo = (size_t)(n0 + r) * DMODEL + l_c16 * 8;
            CP16(dst + POW_H, Wh + wo);
            CP16(dst + POW_L, Wl + wo);
        }
        CP_COMMIT();
    }

    for (int c = 0; c < 16; ++c) {
        if (c + 1 < 16) {
            const int k0 = (c + 1) * 64;
            const uint32_t stb = sbase + ((c + 1) & 1) * PSTG;
            #pragma unroll
            for (int j = 0; j < 4; ++j) {
                int r = l_r + j * 16;
                uint32_t dst = stb + swz(r * 128 + l_c16 * 16);
                size_t ao = (size_t)(m0 + r) * DMODEL + k0 + l_c16 * 8;
                CP16(dst + POA_H, Ah + ao);
                CP16(dst + POA_L, Al + ao);
            }
            #pragma unroll
            for (int j = 0; j < 8; ++j) {
                int r = l_r + j * 16;
                uint32_t dst = stb + swz(r * 128 + l_c16 * 16);
                size_t wo = (size_t)(n0 + r) * DMODEL + k0 + l_c16 * 8;
                CP16(dst + POW_H, Wh + wo);
                CP16(dst + POW_L, Wl + wo);
            }
            CP_COMMIT();
            CP_WAIT(1);
        } else {
            CP_WAIT(0);
        }
        __syncthreads();

        const uint32_t sst = sbase + (c & 1) * PSTG;
        #pragma unroll
        for (int kk = 0; kk < 4; ++kk) {
            const uint32_t kb = kk * 32;

            uint32_t ah[2][4], al[2][4];
            #pragma unroll
            for (int mt = 0; mt < 2; mt++) {
                uint32_t bo = (a_row + mt * 16) * 128 + kb + a_kb0;
                ldsm4(ah[mt], sst + POA_H + swz(bo));
                ldsm4(al[mt], sst + POA_L + swz(bo));
            }
            uint32_t bh[8][2], bl[8][2];
            #pragma unroll
            for (int np = 0; np < 4; np++) {
                uint32_t bo = (b_row + np * 16) * 128 + kb + b_kb0;
                uint32_t t[4];
                ldsm4(t, sst + POW_H + swz(bo));
                bh[np*2+0][0] = t[0]; bh[np*2+0][1] = t[1];
                bh[np*2+1][0] = t[2]; bh[np*2+1][1] = t[3];
                ldsm4(t, sst + POW_L + swz(bo));
                bl[np*2+0][0] = t[0]; bl[np*2+0][1] = t[1];
                bl[np*2+1][0] = t[2]; bl[np*2+1][1] = t[3];
            }
            #pragma unroll
            for (int mt = 0; mt < 2; mt++)
                #pragma unroll
                for (int nt = 0; nt < 8; nt++) {
                    mma16816(acc[mt][nt], ah[mt], bh[nt]);
                    mma16816(acc[mt][nt], al[mt], bh[nt]);
                    mma16816(acc[mt][nt], ah[mt], bl[nt]);
                }
        }
        __syncthreads();
    }

    // epilogue: scale, split to bf16 hi/lo planes at [b,h,l,e]
    const int gid = lane >> 2;
    const int qid = lane & 3;
    #pragma unroll
    for (int mt = 0; mt < 2; mt++) {
        int m  = m0 + wm + mt * 16 + gid;
        int bb = m >> 10;
        int l  = m & 1023;
        #pragma unroll
        for (int nt = 0; nt < 8; nt++) {
            int n = n0 + wn + nt * 8 + qid * 2;
            int hh = n >> 6;
            int e  = n & 63;
            size_t idx0 = (((size_t)(bb * HEADS + hh) * SEQ + l) * DEPTH + e);
            size_t idx1 = idx0 + 8 * DEPTH;
            uint32_t hi, lo;
            split2(acc[mt][nt][0] * scale, acc[mt][nt][1] * scale, hi, lo);
            *(uint32_t*)(outh + idx0) = hi;
            *(uint32_t*)(outl + idx0) = lo;
            split2(acc[mt][nt][2] * scale, acc[mt][nt][3] * scale, hi, lo);
            *(uint32_t*)(outh + idx1) = hi;
            *(uint32_t*)(outl + idx1) = lo;
        }
    }
}

// ===========================================================================
// Flash attention: unchanged from R6 (known correct, ~80% of HMMA floor)
// smem: KV stage0 32K | KV stage1 32K | Q 16K = 80KB ; 2 CTAs/SM
// ===========================================================================
#define ATTN_SMEM 81920
#define KSTG 32768
#define AQH  65536
#define AQL  73728

__global__ __launch_bounds__(128, 2)
void mma_attn_kernel(float* __restrict__ out,
                     const __nv_bfloat16* __restrict__ Qh, const __nv_bfloat16* __restrict__ Ql,
                     const __nv_bfloat16* __restrict__ Kh, const __nv_bfloat16* __restrict__ Kl,
                     const __nv_bfloat16* __restrict__ Vh, const __nv_bfloat16* __restrict__ Vl)
{
    extern __shared__ char smc[];
    const uint32_t sb = smem_u32(smc);
    const int tid  = threadIdx.x;
    const int lane = tid & 31;
    const int wid  = tid >> 5;
    const int qt   = blockIdx.x;
    const int h    = blockIdx.y;
    const int b    = blockIdx.z;

    const size_t base = (size_t)(b * HEADS + h) * SEQ * DEPTH;
    const __nv_bfloat16* qhp = Qh + base + (size_t)(qt * 64) * DEPTH;
    const __nv_bfloat16* qlp = Ql + base + (size_t)(qt * 64) * DEPTH;
    const __nv_bfloat16* khp = Kh + base;
    const __nv_bfloat16* klp = Kl + base;
    const __nv_bfloat16* vhp = Vh + base;
    const __nv_bfloat16* vlp = Vl + base;

    const int l_r   = tid >> 3;
    const int l_c16 = tid & 7;

    // prologue: Q planes + KV tile 0
    {
        #pragma unroll
        for (int j = 0; j < 4; ++j) {
            int r = l_r + j * 16;
            uint32_t dst = sb + swz(r * 128 + l_c16 * 16);
            size_t qo = (size_t)r * DEPTH + l_c16 * 8;
            CP16(dst + AQH, qhp + qo);
            CP16(dst + AQL, qlp + qo);
        }
        #pragma unroll
        for (int j = 0; j < 4; ++j) {
            int r = l_r + j * 16;
            uint32_t dst = sb + swz(r * 128 + l_c16 * 16);
            size_t so = (size_t)r * DEPTH + l_c16 * 8;
            CP16(dst +     0, khp + so);
            CP16(dst +  8192, klp + so);
            CP16(dst + 16384, vhp + so);
            CP16(dst + 24576, vlp + so);
        }
        CP_COMMIT();
        CP_WAIT(0);
    }
    __syncthreads();

    const int wm = wid * 16;
    const uint32_t qa_row = wm + (lane & 15);
    const uint32_t qa_cb  = (lane >> 4) << 4;
    const uint32_t kb_row = (lane & 7) + (((lane >> 4) & 1) << 3);
    const uint32_t kb_cb  = ((lane >> 3) & 1) << 4;
    const uint32_t va_row = (((lane >> 3) & 1) << 3) + (lane & 7);
    const uint32_t va_cb  = (lane >> 4) << 4;

    uint32_t qh[4][4], ql[4][4];
    #pragma unroll
    for (int kk = 0; kk < 4; ++kk) {
        uint32_t qoff = qa_row * 128 + kk * 32 + qa_cb;
        ldsm4(qh[kk], sb + AQH + swz(qoff));
        ldsm4(ql[kk], sb + AQL + swz(qoff));
    }

    float m0 = -1e30f, m1 = -1e30f, l0 = 0.f, l1 = 0.f;
    float o[8][4];
    #pragma unroll
    for (int j = 0; j < 8; j++)
        #pragma unroll
        for (int r = 0; r < 4; r++) o[j][r] = 0.f;

    for (int t = 0; t < 16; ++t) {
        if (t + 1 < 16) {
            const uint32_t stb = sb + ((t + 1) & 1) * KSTG;
            #pragma unroll
            for (int j = 0; j < 4; ++j) {
                int r = l_r + j * 16;
                uint32_t dst = stb + swz(r * 128 + l_c16 * 16);
                size_t so = (size_t)((t + 1) * 64 + r) * DEPTH + l_c16 * 8;
                CP16(dst +     0, khp + so);
                CP16(dst +  8192, klp + so);
                CP16(dst + 16384, vhp + so);
                CP16(dst + 24576, vlp + so);
            }
            CP_COMMIT();
            CP_WAIT(1);
        } else {
            CP_WAIT(0);
        }
        __syncthreads();

        const uint32_t st = sb + (t & 1) * KSTG;

        // ---- S = Q Kt (3 split passes) ----
        float s[8][4];
        #pragma unroll
        for (int j = 0; j < 8; j++)
            #pragma unroll
            for (int r = 0; r < 4; r++) s[j][r] = 0.f;

        #pragma unroll
        for (int kk = 0; kk < 4; ++kk) {
            #pragma unroll
            for (int np = 0; np < 4; ++np) {
                uint32_t koff = (np * 16 + kb_row) * 128 + kk * 32 + kb_cb;
                uint32_t th[4], tl[4];
                ldsm4(th, st +    0 + swz(koff));
                ldsm4(tl, st + 8192 + swz(koff));
                mma16816(s[np*2+0], qh[kk], th + 0);
                mma16816(s[np*2+0], ql[kk], th + 0);
                mma16816(s[np*2+0], qh[kk], tl + 0);
                mma16816(s[np*2+1], qh[kk], th + 2);
                mma16816(s[np*2+1], ql[kk], th + 2);
                mma16816(s[np*2+1], qh[kk], tl + 2);
            }
        }

        // ---- online softmax (log2 domain) ----
        float mx0 = s[0][0], mx1 = s[0][2];
        #pragma unroll
        for (int j = 0; j < 8; j++) {
            mx0 = fmaxf(mx0, fmaxf(s[j][0], s[j][1]));
            mx1 = fmaxf(mx1, fmaxf(s[j][2], s[j][3]));
        }
        mx0 = fmaxf(mx0, __shfl_xor_sync(0xffffffffu, mx0, 1));
        mx0 = fmaxf(mx0, __shfl_xor_sync(0xffffffffu, mx0, 2));
        mx1 = fmaxf(mx1, __shfl_xor_sync(0xffffffffu, mx1, 1));
        mx1 = fmaxf(mx1, __shfl_xor_sync(0xffffffffu, mx1, 2));

        float mn0 = fmaxf(m0, mx0), mn1 = fmaxf(m1, mx1);
        float sc0 = ex2(m0 - mn0),  sc1 = ex2(m1 - mn1);
        m0 = mn0; m1 = mn1;

        float rs0 = 0.f, rs1 = 0.f;
        uint32_t ph[8][2], pl[8][2];
        #pragma unroll
        for (int j = 0; j < 8; j++) {
            float p0 = ex2(s[j][0] - m0);
            float p1 = ex2(s[j][1] - m0);
            float p2 = ex2(s[j][2] - m1);
            float p3 = ex2(s[j][3] - m1);
            rs0 += p0 + p1;
            rs1 += p2 + p3;
            ph[j][0] = packbf(p0, p1);
            ph[j][1] = packbf(p2, p3);
            pl[j][0] = packbf(p0 - ubf_lo(ph[j][0]), p1 - ubf_hi(ph[j][0]));
            pl[j][1] = packbf(p2 - ubf_lo(ph[j][1]), p3 - ubf_hi(ph[j][1]));
        }
        rs0 += __shfl_xor_sync(0xffffffffu, rs0, 1);
        rs0 += __shfl_xor_sync(0xffffffffu, rs0, 2);
        rs1 += __shfl_xor_sync(0xffffffffu, rs1, 1);
        rs1 += __shfl_xor_sync(0xffffffffu, rs1, 2);
        l0 = l0 * sc0 + rs0;
        l1 = l1 * sc1 + rs1;
        #pragma unroll
        for (int j = 0; j < 8; j++) {
            o[j][0] *= sc0; o[j][1] *= sc0;
            o[j][2] *= sc1; o[j][3] *= sc1;
        }

        // ---- O += P V (3 split passes), V via trans ldmatrix ----
        #pragma unroll
        for (int ks = 0; ks < 4; ++ks) {
            uint32_t ah[4] = { ph[ks*2][0], ph[ks*2][1], ph[ks*2+1][0], ph[ks*2+1][1] };
            uint32_t al[4] = { pl[ks*2][0], pl[ks*2][1], pl[ks*2+1][0], pl[ks*2+1][1] };
            #pragma unroll
            for (int dg = 0; dg < 4; ++dg) {
                uint32_t voff = (ks * 16 + va_row) * 128 + dg * 32 + va_cb;
                uint32_t th[4], tl[4];
                ldsm4t(th, st + 16384 + swz(voff));
                ldsm4t(tl, st + 24576 + swz(voff));
                mma16816(o[dg*2+0], ah, th + 0);
                mma16816(o[dg*2+0], al, th + 0);
                mma16816(o[dg*2+0], ah, tl + 0);
                mma16816(o[dg*2+1], ah, th + 2);
                mma16816(o[dg*2+1], al, th + 2);
                mma16816(o[dg*2+1], ah, tl + 2);
            }
        }
        __syncthreads();
    }

    // ---- epilogue: normalize, store to [B, L, H*DEPTH] ----
    float inv0 = 1.f / l0, inv1 = 1.f / l1;
    int r0 = qt * 64 + wm + (lane >> 2);
    float* p0 = out + ((size_t)b * SEQ + r0) * (HEADS * DEPTH) + h * DEPTH + (lane & 3) * 2;
    float* p1 = p0 + 8 * (HEADS * DEPTH);
    #pragma unroll
    for (int j = 0; j < 8; j++) {
        *(float2*)(p0 + j * 8) = make_float2(o[j][0] * inv0, o[j][1] * inv0);
        *(float2*)(p1 + j * 8) = make_float2(o[j][2] * inv1, o[j][3] * inv1);
    }
}

// ===========================================================================
extern "C" void kernel_launch(void* const* d_in, const int* in_sizes, int n_in,
                              void* d_out, int out_size)
{
    const float* query  = (const float*)d_in[0];
    const float* keys   = (const float*)d_in[1];
    const float* values = (const float*)d_in[2];
    const float* Wq     = (const float*)d_in[3];
    const float* Wk     = (const float*)d_in[4];
    const float* Wv     = (const float*)d_in[5];
    float* out = (float*)d_out;

    __nv_bfloat16 *xh, *xl, *wh, *wl, *ph, *pl;
    cudaGetSymbolAddress((void**)&xh, g_xh);
    cudaGetSymbolAddress((void**)&xl, g_xl);
    cudaGetSymbolAddress((void**)&wh, g_wh);
    cudaGetSymbolAddress((void**)&wl, g_wl);
    cudaGetSymbolAddress((void**)&ph, g_ph);
    cudaGetSymbolAddress((void**)&pl, g_pl);

    cudaFuncSetAttribute(mma_proj_kernel,
                         cudaFuncAttributeMaxDynamicSharedMemorySize, PROJ_SMEM);
    cudaFuncSetAttribute(mma_attn_kernel,
                         cudaFuncAttributeMaxDynamicSharedMemorySize, ATTN_SMEM);

    // presplit: inputs (one launch) and weights (one launch)
    {
        dim3 g1(IN_N/4/256, 3);
        presplit3_kernel<<<g1, 256>>>((const float4*)query, (const float4*)keys,
                                      (const float4*)values,
                                      (uint2*)xh, (uint2*)xl, IN_N/4);
        dim3 g2(W_N/4/256, 3);
        presplit3_kernel<<<g2, 256>>>((const float4*)Wq, (const float4*)Wk,
                                      (const float4*)Wv,
                                      (uint2*)wh, (uint2*)wl, W_N/4);
    }

    dim3 pgrid(DMODEL / 128, (BATCH * SEQ) / 64, 3);    // (8, 128, 3)
    mma_proj_kernel<<<pgrid, 128, PROJ_SMEM>>>(xh, xl, wh, wl, ph, pl);

    dim3 agrid(SEQ / 64, HEADS, BATCH);                 // (16, 16, 8)
    mma_attn_kernel<<<agrid, 128, ATTN_SMEM>>>(out,
        ph + 0,              pl + 0,
        ph + (size_t)IN_N,   pl + (size_t)IN_N,
        ph + (size_t)2*IN_N, pl + (size_t)2*IN_N);
}

// round 8
// speedup vs baseline: 4.5619x; 1.0020x over previous
#include <cuda_runtime.h>
#include <cuda_bf16.h>
#include <cstdint>

#define BATCH  8
#define HEADS  16
#define SEQ    1024
#define DMODEL 1024
#define DEPTH  64

#define IN_N   (BATCH*SEQ*DMODEL)      // 8388608  (== BATCH*HEADS*SEQ*DEPTH)
#define W_N    (DMODEL*DMODEL)         // 1048576
#define QSCALE 0.18033688f             /* 0.125 * log2(e) */

// bf16 hi/lo planes: presplit inputs, presplit weights, projected q/k/v
__device__ __nv_bfloat16 g_xh[3*IN_N];
__device__ __nv_bfloat16 g_xl[3*IN_N];
__device__ __nv_bfloat16 g_wh[3*W_N];
__device__ __nv_bfloat16 g_wl[3*W_N];
__device__ __nv_bfloat16 g_ph[3*IN_N];
__device__ __nv_bfloat16 g_pl[3*IN_N];

// ===========================================================================
// Helpers (base PTX only — valid at compute_103)
// ===========================================================================
__device__ __forceinline__ uint32_t smem_u32(const void* p) {
    uint32_t a;
    asm("{ .reg .u64 t; cvta.to.shared.u64 t, %1; cvt.u32.u64 %0, t; }"
        : "=r"(a) : "l"(p));
    return a;
}
__device__ __forceinline__ void ldsm4(uint32_t* r, uint32_t addr) {
    asm volatile("ldmatrix.sync.aligned.m8n8.x4.shared.b16 {%0,%1,%2,%3}, [%4];"
                 : "=r"(r[0]), "=r"(r[1]), "=r"(r[2]), "=r"(r[3]) : "r"(addr));
}
__device__ __forceinline__ void ldsm4t(uint32_t* r, uint32_t addr) {
    asm volatile("ldmatrix.sync.aligned.m8n8.x4.trans.shared.b16 {%0,%1,%2,%3}, [%4];"
                 : "=r"(r[0]), "=r"(r[1]), "=r"(r[2]), "=r"(r[3]) : "r"(addr));
}
__device__ __forceinline__ void mma16816(float* d, const uint32_t* a, const uint32_t* b) {
    asm volatile("mma.sync.aligned.m16n8k16.row.col.f32.bf16.bf16.f32 "
                 "{%0,%1,%2,%3}, {%4,%5,%6,%7}, {%8,%9}, {%0,%1,%2,%3};"
                 : "+f"(d[0]), "+f"(d[1]), "+f"(d[2]), "+f"(d[3])
                 : "r"(a[0]), "r"(a[1]), "r"(a[2]), "r"(a[3]),
                   "r"(b[0]), "r"(b[1]));
}
__device__ __forceinline__ uint32_t swz(uint32_t bo) { return bo ^ ((bo >> 3) & 0x70); }
__device__ __forceinline__ float ex2(float x) {
    float r; asm("ex2.approx.f32 %0, %1;" : "=f"(r) : "f"(x)); return r;
}
__device__ __forceinline__ void split2(float x0, float x1, uint32_t& hi, uint32_t& lo) {
    __nv_bfloat162 h = __floats2bfloat162_rn(x0, x1);
    hi = *reinterpret_cast<uint32_t*>(&h);
    float r0 = x0 - __bfloat162float(h.x);
    float r1 = x1 - __bfloat162float(h.y);
    __nv_bfloat162 l = __floats2bfloat162_rn(r0, r1);
    lo = *reinterpret_cast<uint32_t*>(&l);
}
__device__ __forceinline__ uint32_t packbf(float lo, float hi) {
    __nv_bfloat162 h = __floats2bfloat162_rn(lo, hi);
    return *reinterpret_cast<uint32_t*>(&h);
}
__device__ __forceinline__ float ubf_lo(uint32_t p) { return __uint_as_float(p << 16); }
__device__ __forceinline__ float ubf_hi(uint32_t p) { return __uint_as_float(p & 0xFFFF0000u); }

#define CP16(dst, src) \
    asm volatile("cp.async.cg.shared.global [%0], [%1], 16;" :: "r"(dst), "l"(src))
#define CP_COMMIT() asm volatile("cp.async.commit_group;" ::: "memory")
#define CP_WAIT(n)  asm volatile("cp.async.wait_group %0;" :: "n"(n) : "memory")

// ===========================================================================
// Presplit: fp32 -> bf16 hi/lo planes; z dimension picks source array
// ===========================================================================
__global__ void presplit3_kernel(const float4* __restrict__ s0,
                                 const float4* __restrict__ s1,
                                 const float4* __restrict__ s2,
                                 uint2* __restrict__ dh, uint2* __restrict__ dl,
                                 int n4)
{
    int i = blockIdx.x * blockDim.x + threadIdx.x;
    if (i >= n4) return;
    int z = blockIdx.y;
    const float4* src = (z == 0) ? s0 : (z == 1) ? s1 : s2;
    float4 v = src[i];
    uint32_t h01, l01, h23, l23;
    split2(v.x, v.y, h01, l01);
    split2(v.z, v.w, h23, l23);
    dh[(size_t)z * n4 + i] = make_uint2(h01, h23);
    dl[(size_t)z * n4 + i] = make_uint2(l01, l23);
}

// ===========================================================================
// Projection GEMM (unchanged from R7): 128 thr, tile 64x128, 2 CTAs/SM
// ===========================================================================
#define PSTG      49152
#define PROJ_SMEM (2*PSTG)
#define POA_H 0
#define POA_L 8192
#define POW_H 16384
#define POW_L 32768

__global__ __launch_bounds__(128, 2)
void mma_proj_kernel(const __nv_bfloat16* __restrict__ AhG, const __nv_bfloat16* __restrict__ AlG,
                     const __nv_bfloat16* __restrict__ WhG, const __nv_bfloat16* __restrict__ WlG,
                     __nv_bfloat16* __restrict__ outhG, __nv_bfloat16* __restrict__ outlG)
{
    extern __shared__ char smc[];
    const uint32_t sbase = smem_u32(smc);
    const int tid  = threadIdx.x;
    const int lane = tid & 31;
    const int wid  = tid >> 5;
    const int n0   = blockIdx.x * 128;
    const int m0   = blockIdx.y * 64;
    const int z    = blockIdx.z;

    const __nv_bfloat16* Ah = AhG + (size_t)z * IN_N;
    const __nv_bfloat16* Al = AlG + (size_t)z * IN_N;
    const __nv_bfloat16* Wh = WhG + (size_t)z * W_N;
    const __nv_bfloat16* Wl = WlG + (size_t)z * W_N;
    __nv_bfloat16* outh = outhG + (size_t)z * IN_N;
    __nv_bfloat16* outl = outlG + (size_t)z * IN_N;
    const float scale = (z == 0) ? QSCALE : 1.0f;

    const int wm = (wid & 1) * 32;
    const int wn = (wid >> 1) * 64;

    float acc[2][8][4];
    #pragma unroll
    for (int mt = 0; mt < 2; mt++)
        #pragma unroll
        for (int nt = 0; nt < 8; nt++)
            #pragma unroll
            for (int r = 0; r < 4; r++) acc[mt][nt][r] = 0.f;

    const uint32_t a_row = wm + (lane & 15);
    const uint32_t a_kb0 = (lane >> 4) << 4;
    const uint32_t b_j   = lane >> 3;
    const uint32_t b_row = wn + (lane & 7) + ((b_j >> 1) << 3);
    const uint32_t b_kb0 = (b_j & 1) << 4;

    const int l_r   = tid >> 3;
    const int l_c16 = tid & 7;

    {
        #pragma unroll
        for (int j = 0; j < 4; ++j) {
            int r = l_r + j * 16;
            uint32_t dst = sbase + swz(r * 128 + l_c16 * 16);
            size_t ao = (size_t)(m0 + r) * DMODEL + l_c16 * 8;
            CP16(dst + POA_H, Ah + ao);
            CP16(dst + POA_L, Al + ao);
        }
        #pragma unroll
        for (int j = 0; j < 8; ++j) {
            int r = l_r + j * 16;
            uint32_t dst = sbase + swz(r * 128 + l_c16 * 16);
            size_t wo = (size_t)(n0 + r) * DMODEL + l_c16 * 8;
            CP16(dst + POW_H, Wh + wo);
            CP16(dst + POW_L, Wl + wo);
        }
        CP_COMMIT();
    }

    for (int c = 0; c < 16; ++c) {
        if (c + 1 < 16) {
            const int k0 = (c + 1) * 64;
            const uint32_t stb = sbase + ((c + 1) & 1) * PSTG;
            #pragma unroll
            for (int j = 0; j < 4; ++j) {
                int r = l_r + j * 16;
                uint32_t dst = stb + swz(r * 128 + l_c16 * 16);
                size_t ao = (size_t)(m0 + r) * DMODEL + k0 + l_c16 * 8;
                CP16(dst + POA_H, Ah + ao);
                CP16(dst + POA_L, Al + ao);
            }
            #pragma unroll
            for (int j = 0; j < 8; ++j) {
                int r = l_r + j * 16;
                uint32_t dst = stb + swz(r * 128 + l_c16 * 16);
                size_t wo = (size_t)(n0 + r) * DMODEL + k0 + l_c16 * 8;
                CP16(dst + POW_H, Wh + wo);
                CP16(dst + POW_L, Wl + wo);
            }
            CP_COMMIT();
            CP_WAIT(1);
        } else {
            CP_WAIT(0);
        }
        __syncthreads();

        const uint32_t sst = sbase + (c & 1) * PSTG;
        #pragma unroll
        for (int kk = 0; kk < 4; ++kk) {
            const uint32_t kb = kk * 32;

            uint32_t ah[2][4], al[2][4];
            #pragma unroll
            for (int mt = 0; mt < 2; mt++) {
                uint32_t bo = (a_row + mt * 16) * 128 + kb + a_kb0;
                ldsm4(ah[mt], sst + POA_H + swz(bo));
                ldsm4(al[mt], sst + POA_L + swz(bo));
            }
            uint32_t bh[8][2], bl[8][2];
            #pragma unroll
            for (int np = 0; np < 4; np++) {
                uint32_t bo = (b_row + np * 16) * 128 + kb + b_kb0;
                uint32_t t[4];
                ldsm4(t, sst + POW_H + swz(bo));
                bh[np*2+0][0] = t[0]; bh[np*2+0][1] = t[1];
                bh[np*2+1][0] = t[2]; bh[np*2+1][1] = t[3];
                ldsm4(t, sst + POW_L + swz(bo));
                bl[np*2+0][0] = t[0]; bl[np*2+0][1] = t[1];
                bl[np*2+1][0] = t[2]; bl[np*2+1][1] = t[3];
            }
            #pragma unroll
            for (int mt = 0; mt < 2; mt++)
                #pragma unroll
                for (int nt = 0; nt < 8; nt++) {
                    mma16816(acc[mt][nt], ah[mt], bh[nt]);
                    mma16816(acc[mt][nt], al[mt], bh[nt]);
                    mma16816(acc[mt][nt], ah[mt], bl[nt]);
                }
        }
        __syncthreads();
    }

    const int gid = lane >> 2;
    const int qid = lane & 3;
    #pragma unroll
    for (int mt = 0; mt < 2; mt++) {
        int m  = m0 + wm + mt * 16 + gid;
        int bb = m >> 10;
        int l  = m & 1023;
        #pragma unroll
        for (int nt = 0; nt < 8; nt++) {
            int n = n0 + wn + nt * 8 + qid * 2;
            int hh = n >> 6;
            int e  = n & 63;
            size_t idx0 = (((size_t)(bb * HEADS + hh) * SEQ + l) * DEPTH + e);
            size_t idx1 = idx0 + 8 * DEPTH;
            uint32_t hi, lo;
            split2(acc[mt][nt][0] * scale, acc[mt][nt][1] * scale, hi, lo);
            *(uint32_t*)(outh + idx0) = hi;
            *(uint32_t*)(outl + idx0) = lo;
            split2(acc[mt][nt][2] * scale, acc[mt][nt][3] * scale, hi, lo);
            *(uint32_t*)(outh + idx1) = hi;
            *(uint32_t*)(outl + idx1) = lo;
        }
    }
}

// ===========================================================================
// Flash attention: 4 warps, warp q-tile 32 rows (2 m-frags) -> CTA 128 rows.
// K/V fragment loads amortized over 2x q-rows => smem crossbar no longer binds.
// smem: KV stage0 32K | KV stage1 32K | Qh 16K | Ql 16K = 96KB ; 2 CTAs/SM
// ===========================================================================
#define ATTN_SMEM 98304
#define KSTG 32768
#define AQH  65536
#define AQL  81920

__global__ __launch_bounds__(128, 2)
void mma_attn_kernel(float* __restrict__ out,
                     const __nv_bfloat16* __restrict__ Qh, const __nv_bfloat16* __restrict__ Ql,
                     const __nv_bfloat16* __restrict__ Kh, const __nv_bfloat16* __restrict__ Kl,
                     const __nv_bfloat16* __restrict__ Vh, const __nv_bfloat16* __restrict__ Vl)
{
    extern __shared__ char smc[];
    const uint32_t sb = smem_u32(smc);
    const int tid  = threadIdx.x;
    const int lane = tid & 31;
    const int wid  = tid >> 5;
    const int qt   = blockIdx.x;
    const int h    = blockIdx.y;
    const int b    = blockIdx.z;

    const size_t base = (size_t)(b * HEADS + h) * SEQ * DEPTH;
    const __nv_bfloat16* qhp = Qh + base + (size_t)(qt * 128) * DEPTH;
    const __nv_bfloat16* qlp = Ql + base + (size_t)(qt * 128) * DEPTH;
    const __nv_bfloat16* khp = Kh + base;
    const __nv_bfloat16* klp = Kl + base;
    const __nv_bfloat16* vhp = Vh + base;
    const __nv_bfloat16* vlp = Vl + base;

    const int l_r   = tid >> 3;     // 0..15, rows advance by 16
    const int l_c16 = tid & 7;

    // prologue: Q planes (128 rows) + KV tile 0 (64 rows)
    {
        #pragma unroll
        for (int j = 0; j < 8; ++j) {
            int r = l_r + j * 16;
            uint32_t dst = sb + swz(r * 128 + l_c16 * 16);
            size_t qo = (size_t)r * DEPTH + l_c16 * 8;
            CP16(dst + AQH, qhp + qo);
            CP16(dst + AQL, qlp + qo);
        }
        #pragma unroll
        for (int j = 0; j < 4; ++j) {
            int r = l_r + j * 16;
            uint32_t dst = sb + swz(r * 128 + l_c16 * 16);
            size_t so = (size_t)r * DEPTH + l_c16 * 8;
            CP16(dst +     0, khp + so);
            CP16(dst +  8192, klp + so);
            CP16(dst + 16384, vhp + so);
            CP16(dst + 24576, vlp + so);
        }
        CP_COMMIT();
        CP_WAIT(0);
    }
    __syncthreads();

    const int wm = wid * 32;                 // warp covers 32 q rows
    const uint32_t qa_row = wm + (lane & 15);
    const uint32_t qa_cb  = (lane >> 4) << 4;
    const uint32_t kb_row = (lane & 7) + (((lane >> 4) & 1) << 3);
    const uint32_t kb_cb  = ((lane >> 3) & 1) << 4;
    const uint32_t va_row = (((lane >> 3) & 1) << 3) + (lane & 7);
    const uint32_t va_cb  = (lane >> 4) << 4;

    // hoist Q fragments (2 m-frags x 4 k-steps x 2 planes)
    uint32_t qh[2][4][4], ql[2][4][4];
    #pragma unroll
    for (int mt = 0; mt < 2; ++mt)
        #pragma unroll
        for (int kk = 0; kk < 4; ++kk) {
            uint32_t qoff = (qa_row + mt * 16) * 128 + kk * 32 + qa_cb;
            ldsm4(qh[mt][kk], sb + AQH + swz(qoff));
            ldsm4(ql[mt][kk], sb + AQL + swz(qoff));
        }

    float mrow[2][2], lrow[2][2];
    float o[2][8][4];
    #pragma unroll
    for (int mt = 0; mt < 2; mt++) {
        mrow[mt][0] = -1e30f; mrow[mt][1] = -1e30f;
        lrow[mt][0] = 0.f;    lrow[mt][1] = 0.f;
        #pragma unroll
        for (int j = 0; j < 8; j++)
            #pragma unroll
            for (int r = 0; r < 4; r++) o[mt][j][r] = 0.f;
    }

    for (int t = 0; t < 16; ++t) {
        if (t + 1 < 16) {
            const uint32_t stb = sb + ((t + 1) & 1) * KSTG;
            #pragma unroll
            for (int j = 0; j < 4; ++j) {
                int r = l_r + j * 16;
                uint32_t dst = stb + swz(r * 128 + l_c16 * 16);
                size_t so = (size_t)((t + 1) * 64 + r) * DEPTH + l_c16 * 8;
                CP16(dst +     0, khp + so);
                CP16(dst +  8192, klp + so);
                CP16(dst + 16384, vhp + so);
                CP16(dst + 24576, vlp + so);
            }
            CP_COMMIT();
            CP_WAIT(1);
        } else {
            CP_WAIT(0);
        }
        __syncthreads();

        const uint32_t st = sb + (t & 1) * KSTG;

        // ---- S = Q Kt (3 split passes); K frags shared across both m-frags
        float s[2][8][4];
        #pragma unroll
        for (int mt = 0; mt < 2; mt++)
            #pragma unroll
            for (int j = 0; j < 8; j++)
                #pragma unroll
                for (int r = 0; r < 4; r++) s[mt][j][r] = 0.f;

        #pragma unroll
        for (int kk = 0; kk < 4; ++kk) {
            #pragma unroll
            for (int np = 0; np < 4; ++np) {
                uint32_t koff = (np * 16 + kb_row) * 128 + kk * 32 + kb_cb;
                uint32_t th[4], tl[4];
                ldsm4(th, st +    0 + swz(koff));
                ldsm4(tl, st + 8192 + swz(koff));
                #pragma unroll
                for (int mt = 0; mt < 2; mt++) {
                    mma16816(s[mt][np*2+0], qh[mt][kk], th + 0);
                    mma16816(s[mt][np*2+0], ql[mt][kk], th + 0);
                    mma16816(s[mt][np*2+0], qh[mt][kk], tl + 0);
                    mma16816(s[mt][np*2+1], qh[mt][kk], th + 2);
                    mma16816(s[mt][np*2+1], ql[mt][kk], th + 2);
                    mma16816(s[mt][np*2+1], qh[mt][kk], tl + 2);
                }
            }
        }

        // ---- online softmax (log2 domain), per m-frag ----
        uint32_t ph[2][8][2], pl[2][8][2];
        #pragma unroll
        for (int mt = 0; mt < 2; mt++) {
            float mx0 = s[mt][0][0], mx1 = s[mt][0][2];
            #pragma unroll
            for (int j = 0; j < 8; j++) {
                mx0 = fmaxf(mx0, fmaxf(s[mt][j][0], s[mt][j][1]));
                mx1 = fmaxf(mx1, fmaxf(s[mt][j][2], s[mt][j][3]));
            }
            mx0 = fmaxf(mx0, __shfl_xor_sync(0xffffffffu, mx0, 1));
            mx0 = fmaxf(mx0, __shfl_xor_sync(0xffffffffu, mx0, 2));
            mx1 = fmaxf(mx1, __shfl_xor_sync(0xffffffffu, mx1, 1));
            mx1 = fmaxf(mx1, __shfl_xor_sync(0xffffffffu, mx1, 2));

            float mn0 = fmaxf(mrow[mt][0], mx0), mn1 = fmaxf(mrow[mt][1], mx1);
            float sc0 = ex2(mrow[mt][0] - mn0),  sc1 = ex2(mrow[mt][1] - mn1);
            mrow[mt][0] = mn0; mrow[mt][1] = mn1;

            float rs0 = 0.f, rs1 = 0.f;
            #pragma unroll
            for (int j = 0; j < 8; j++) {
                float p0 = ex2(s[mt][j][0] - mn0);
                float p1 = ex2(s[mt][j][1] - mn0);
                float p2 = ex2(s[mt][j][2] - mn1);
                float p3 = ex2(s[mt][j][3] - mn1);
                rs0 += p0 + p1;
                rs1 += p2 + p3;
                ph[mt][j][0] = packbf(p0, p1);
                ph[mt][j][1] = packbf(p2, p3);
                pl[mt][j][0] = packbf(p0 - ubf_lo(ph[mt][j][0]), p1 - ubf_hi(ph[mt][j][0]));
                pl[mt][j][1] = packbf(p2 - ubf_lo(ph[mt][j][1]), p3 - ubf_hi(ph[mt][j][1]));
            }
            rs0 += __shfl_xor_sync(0xffffffffu, rs0, 1);
            rs0 += __shfl_xor_sync(0xffffffffu, rs0, 2);
            rs1 += __shfl_xor_sync(0xffffffffu, rs1, 1);
            rs1 += __shfl_xor_sync(0xffffffffu, rs1, 2);
            lrow[mt][0] = lrow[mt][0] * sc0 + rs0;
            lrow[mt][1] = lrow[mt][1] * sc1 + rs1;
            #pragma unroll
            for (int j = 0; j < 8; j++) {
                o[mt][j][0] *= sc0; o[mt][j][1] *= sc0;
                o[mt][j][2] *= sc1; o[mt][j][3] *= sc1;
            }
        }

        // ---- O += P V (3 split passes); V frags shared across both m-frags
        #pragma unroll
        for (int ks = 0; ks < 4; ++ks) {
            #pragma unroll
            for (int dg = 0; dg < 4; ++dg) {
                uint32_t voff = (ks * 16 + va_row) * 128 + dg * 32 + va_cb;
                uint32_t th[4], tl[4];
                ldsm4t(th, st + 16384 + swz(voff));
                ldsm4t(tl, st + 24576 + swz(voff));
                #pragma unroll
                for (int mt = 0; mt < 2; mt++) {
                    uint32_t ah[4] = { ph[mt][ks*2][0], ph[mt][ks*2][1],
                                       ph[mt][ks*2+1][0], ph[mt][ks*2+1][1] };
                    uint32_t al[4] = { pl[mt][ks*2][0], pl[mt][ks*2][1],
                                       pl[mt][ks*2+1][0], pl[mt][ks*2+1][1] };
                    mma16816(o[mt][dg*2+0], ah, th + 0);
                    mma16816(o[mt][dg*2+0], al, th + 0);
                    mma16816(o[mt][dg*2+0], ah, tl + 0);
                    mma16816(o[mt][dg*2+1], ah, th + 2);
                    mma16816(o[mt][dg*2+1], al, th + 2);
                    mma16816(o[mt][dg*2+1], ah, tl + 2);
                }
            }
        }
        __syncthreads();
    }

    // ---- epilogue: normalize, store to [B, L, H*DEPTH] ----
    #pragma unroll
    for (int mt = 0; mt < 2; mt++) {
        float inv0 = 1.f / lrow[mt][0], inv1 = 1.f / lrow[mt][1];
        int r0 = qt * 128 + wm + mt * 16 + (lane >> 2);
        float* p0 = out + ((size_t)b * SEQ + r0) * (HEADS * DEPTH) + h * DEPTH + (lane & 3) * 2;
        float* p1 = p0 + 8 * (HEADS * DEPTH);
        #pragma unroll
        for (int j = 0; j < 8; j++) {
            *(float2*)(p0 + j * 8) = make_float2(o[mt][j][0] * inv0, o[mt][j][1] * inv0);
            *(float2*)(p1 + j * 8) = make_float2(o[mt][j][2] * inv1, o[mt][j][3] * inv1);
        }
    }
}

// ===========================================================================
extern "C" void kernel_launch(void* const* d_in, const int* in_sizes, int n_in,
                              void* d_out, int out_size)
{
    const float* query  = (const float*)d_in[0];
    const float* keys   = (const float*)d_in[1];
    const float* values = (const float*)d_in[2];
    const float* Wq     = (const float*)d_in[3];
    const float* Wk     = (const float*)d_in[4];
    const float* Wv     = (const float*)d_in[5];
    float* out = (float*)d_out;

    __nv_bfloat16 *xh, *xl, *wh, *wl, *ph, *pl;
    cudaGetSymbolAddress((void**)&xh, g_xh);
    cudaGetSymbolAddress((void**)&xl, g_xl);
    cudaGetSymbolAddress((void**)&wh, g_wh);
    cudaGetSymbolAddress((void**)&wl, g_wl);
    cudaGetSymbolAddress((void**)&ph, g_ph);
    cudaGetSymbolAddress((void**)&pl, g_pl);

    cudaFuncSetAttribute(mma_proj_kernel,
                         cudaFuncAttributeMaxDynamicSharedMemorySize, PROJ_SMEM);
    cudaFuncSetAttribute(mma_attn_kernel,
                         cudaFuncAttributeMaxDynamicSharedMemorySize, ATTN_SMEM);

    {
        dim3 g1(IN_N/4/256, 3);
        presplit3_kernel<<<g1, 256>>>((const float4*)query, (const float4*)keys,
                                      (const float4*)values,
                                      (uint2*)xh, (uint2*)xl, IN_N/4);
        dim3 g2(W_N/4/256, 3);
        presplit3_kernel<<<g2, 256>>>((const float4*)Wq, (const float4*)Wk,
                                      (const float4*)Wv,
                                      (uint2*)wh, (uint2*)wl, W_N/4);
    }

    dim3 pgrid(DMODEL / 128, (BATCH * SEQ) / 64, 3);    // (8, 128, 3)
    mma_proj_kernel<<<pgrid, 128, PROJ_SMEM>>>(xh, xl, wh, wl, ph, pl);

    dim3 agrid(SEQ / 128, HEADS, BATCH);                // (8, 16, 8)
    mma_attn_kernel<<<agrid, 128, ATTN_SMEM>>>(out,
        ph + 0,              pl + 0,
        ph + (size_t)IN_N,   pl + (size_t)IN_N,
        ph + (size_t)2*IN_N, pl + (size_t)2*IN_N);
}